// round 6
// baseline (speedup 1.0000x reference)
#include <cuda_runtime.h>
#include <cuda_bf16.h>

// Problem dims
#define B_    2
#define L_    2048
#define D_    2048
#define H_    16
#define HD_   128
#define RQ_   1536
#define RKV_  512
#define BL_   (B_ * L_)

#define SCALE_ 0.08838834764831845f  // 1/sqrt(128)

// ---------------- scratch (device globals; no allocation allowed) ----------
__device__ float g_qdown[BL_ * RQ_];   // [4096, 1536]
__device__ float g_q    [BL_ * D_];    // [4096, 2048]  q as [bs, h*128+d]
__device__ float g_c    [BL_ * RKV_];  // [4096, 512]
__device__ float g_k    [BL_ * D_];    // [4096, 2048]  k as [bs, h*128+d]
__device__ float g_v    [BL_ * D_];    // [4096, 2048]
__device__ float g_ao   [BL_ * D_];    // attention out, [bs, h*128+d]

// ---------------- fp32 GEMM: C[M,N] = A[M,K] * op(B) --------------------
// NT=true : B is [N,K] row-major (C[m,n] = sum_k A[m,k] * B[n,k])
// NT=false: B is [K,N] row-major (C[m,n] = sum_k A[m,k] * B[k,n])
// All of M%128==0, N%128==0, K%8==0 hold for every call here.
#define BM 128
#define BN 128
#define BKK 8

template <bool NT>
__global__ __launch_bounds__(256, 2)
void gemm_kernel(const float* __restrict__ A, const float* __restrict__ Bm,
                 float* __restrict__ C, int K, int lda, int ldb, int ldc,
                 long bStride, long cStride)
{
    __shared__ float As[BKK][BM];
    __shared__ float Bs[BKK][BN];

    const int tid  = threadIdx.x;
    const int row0 = blockIdx.y * BM;
    const int col0 = blockIdx.x * BN;
    const float* Bp = Bm + (long)blockIdx.z * bStride;
    float*       Cp = C  + (long)blockIdx.z * cStride;

    // A loader: transpose 128x8 tile into As[kk][m]
    const int am = tid >> 1;
    const int ak = (tid & 1) * 4;
    // B loader indices
    int bn, bk;
    if (NT) { bn = tid >> 1;  bk = (tid & 1) * 4; }
    else    { bk = tid >> 5;  bn = (tid & 31) * 4; }

    const int ty = tid >> 4;   // 0..15
    const int tx = tid & 15;   // 0..15

    float acc[8][8];
#pragma unroll
    for (int i = 0; i < 8; i++)
#pragma unroll
        for (int j = 0; j < 8; j++) acc[i][j] = 0.f;

    // preload tile 0
    float4 pa = *(const float4*)&A[(long)(row0 + am) * lda + ak];
    float4 pb;
    if (NT) pb = *(const float4*)&Bp[(long)(col0 + bn) * ldb + bk];
    else    pb = *(const float4*)&Bp[(long)bk * ldb + col0 + bn];

    As[ak + 0][am] = pa.x; As[ak + 1][am] = pa.y;
    As[ak + 2][am] = pa.z; As[ak + 3][am] = pa.w;
    if (NT) {
        Bs[bk + 0][bn] = pb.x; Bs[bk + 1][bn] = pb.y;
        Bs[bk + 2][bn] = pb.z; Bs[bk + 3][bn] = pb.w;
    } else {
        *(float4*)&Bs[bk][bn] = pb;
    }
    __syncthreads();

    const int nt = K / BKK;
    for (int t = 0; t < nt; ++t) {
        if (t + 1 < nt) {
            const int k0 = (t + 1) * BKK;
            pa = *(const float4*)&A[(long)(row0 + am) * lda + k0 + ak];
            if (NT) pb = *(const float4*)&Bp[(long)(col0 + bn) * ldb + k0 + bk];
            else    pb = *(const float4*)&Bp[(long)(k0 + bk) * ldb + col0 + bn];
        }
#pragma unroll
        for (int kk = 0; kk < BKK; ++kk) {
            float4 a0 = *(float4*)&As[kk][ty * 8];
            float4 a1 = *(float4*)&As[kk][ty * 8 + 4];
            float4 b0 = *(float4*)&Bs[kk][tx * 8];
            float4 b1 = *(float4*)&Bs[kk][tx * 8 + 4];
            float a[8] = {a0.x, a0.y, a0.z, a0.w, a1.x, a1.y, a1.z, a1.w};
            float b[8] = {b0.x, b0.y, b0.z, b0.w, b1.x, b1.y, b1.z, b1.w};
#pragma unroll
            for (int i = 0; i < 8; i++)
#pragma unroll
                for (int j = 0; j < 8; j++)
                    acc[i][j] += a[i] * b[j];
        }
        __syncthreads();
        if (t + 1 < nt) {
            As[ak + 0][am] = pa.x; As[ak + 1][am] = pa.y;
            As[ak + 2][am] = pa.z; As[ak + 3][am] = pa.w;
            if (NT) {
                Bs[bk + 0][bn] = pb.x; Bs[bk + 1][bn] = pb.y;
                Bs[bk + 2][bn] = pb.z; Bs[bk + 3][bn] = pb.w;
            } else {
                *(float4*)&Bs[bk][bn] = pb;
            }
            __syncthreads();
        }
    }

#pragma unroll
    for (int i = 0; i < 8; i++) {
        float* cr = Cp + (long)(row0 + ty * 8 + i) * ldc + col0 + tx * 8;
        *(float4*)&cr[0] = make_float4(acc[i][0], acc[i][1], acc[i][2], acc[i][3]);
        *(float4*)&cr[4] = make_float4(acc[i][4], acc[i][5], acc[i][6], acc[i][7]);
    }
}

// ---------------- flash attention (fp32, causal + ALiBi) -------------------
// grid: (L/64, B*H), 256 threads. BQ=64 queries, BK=64 key tile, d=128.
// Q/K stored transposed in smem ([dd][r]); V direct ([j][dd], stride 132);
// P staged transposed ([j][r], stride 68).
// smem floats: Qs 8192 | KVs 8448 | Ps 4352  -> 20992 floats = 83968 B
#define ATTN_SMEM_BYTES (20992 * 4)

__global__ __launch_bounds__(256, 2)
void attn_kernel(const float* __restrict__ Q, const float* __restrict__ Kg,
                 const float* __restrict__ Vg, float* __restrict__ Og)
{
    extern __shared__ float sm[];
    float* Qs  = sm;                  // [128][64]
    float* KVs = sm + 8192;           // K: [128][64] ; V: [64][132]
    float* Ps  = sm + 8192 + 8448;    // [64][68]

    const int tid = threadIdx.x;
    const int ty = tid >> 4;   // 0..15 -> q rows ty*4..ty*4+3
    const int tx = tid & 15;   // 0..15 -> keys tx*4..+3 / d-cols {tx*4, 64+tx*4}
    const int bh = blockIdx.y;
    const int b  = bh >> 4;
    const int h  = bh & 15;
    const int qt = blockIdx.x;
    const int q0 = qt * 64;
    const long rowbase = (long)b * L_ * D_ + (long)h * HD_;
    const float slope = exp2f(-0.5f * (float)(h + 1));

    // load Q tile transposed: Qs[dd][r]
#pragma unroll
    for (int it = 0; it < 8; ++it) {
        int fid = tid + it * 256;
        int r = fid & 63, dq = (fid >> 6) * 4;
        float4 v = *(const float4*)&Q[rowbase + (long)(q0 + r) * D_ + dq];
        Qs[(dq + 0) * 64 + r] = v.x;
        Qs[(dq + 1) * 64 + r] = v.y;
        Qs[(dq + 2) * 64 + r] = v.z;
        Qs[(dq + 3) * 64 + r] = v.w;
    }

    float m[4], l[4], acc[4][8];
#pragma unroll
    for (int i = 0; i < 4; i++) {
        m[i] = -1e30f; l[i] = 0.f;
#pragma unroll
        for (int c = 0; c < 8; c++) acc[i][c] = 0.f;
    }

    for (int kt = 0; kt <= qt; ++kt) {
        const int j0 = kt * 64;
        // load K tile transposed into KVs[dd][j]
#pragma unroll
        for (int it = 0; it < 8; ++it) {
            int fid = tid + it * 256;
            int r = fid & 63, dq = (fid >> 6) * 4;
            float4 v = *(const float4*)&Kg[rowbase + (long)(j0 + r) * D_ + dq];
            KVs[(dq + 0) * 64 + r] = v.x;
            KVs[(dq + 1) * 64 + r] = v.y;
            KVs[(dq + 2) * 64 + r] = v.z;
            KVs[(dq + 3) * 64 + r] = v.w;
        }
        __syncthreads();   // also guards Qs on first iteration

        // scores: S[4q][4k] over d=128
        float s[4][4];
#pragma unroll
        for (int i = 0; i < 4; i++)
#pragma unroll
            for (int j = 0; j < 4; j++) s[i][j] = 0.f;

#pragma unroll 4
        for (int dd = 0; dd < 128; ++dd) {
            float4 qv = *(float4*)&Qs[dd * 64 + ty * 4];
            float4 kv = *(float4*)&KVs[dd * 64 + tx * 4];
            float qa[4] = {qv.x, qv.y, qv.z, qv.w};
            float ka[4] = {kv.x, kv.y, kv.z, kv.w};
#pragma unroll
            for (int i = 0; i < 4; i++)
#pragma unroll
                for (int j = 0; j < 4; j++)
                    s[i][j] += qa[i] * ka[j];
        }
        __syncthreads();  // done reading KVs (K)

        const bool diag = (kt == qt);
        float alpha[4];
#pragma unroll
        for (int i = 0; i < 4; i++) {
            const int ig = q0 + ty * 4 + i;
            float sv[4];
            float tmax = -1e30f;
#pragma unroll
            for (int j = 0; j < 4; j++) {
                const int jg = j0 + tx * 4 + j;
                float val = s[i][j] * SCALE_ - slope * (float)(ig - jg);
                if (diag && jg > ig) val = -1e30f;
                sv[j] = val;
                tmax = fmaxf(tmax, val);
            }
#pragma unroll
            for (int off = 1; off < 16; off <<= 1)
                tmax = fmaxf(tmax, __shfl_xor_sync(0xffffffffu, tmax, off));
            const float mn = fmaxf(m[i], tmax);
            alpha[i] = __expf(m[i] - mn);
            float ts = 0.f;
#pragma unroll
            for (int j = 0; j < 4; j++) {
                const float p = __expf(sv[j] - mn);
                ts += p;
                Ps[(tx * 4 + j) * 68 + ty * 4 + i] = p;   // transposed stage
            }
#pragma unroll
            for (int off = 1; off < 16; off <<= 1)
                ts += __shfl_xor_sync(0xffffffffu, ts, off);
            l[i] = l[i] * alpha[i] + ts;
            m[i] = mn;
#pragma unroll
            for (int c = 0; c < 8; c++) acc[i][c] *= alpha[i];
        }

        // load V tile (direct) into KVs[j][dd], stride 132
#pragma unroll
        for (int it = 0; it < 8; ++it) {
            int fid = tid + it * 256;
            int j = fid >> 5, dq = (fid & 31) * 4;
            float4 v = *(const float4*)&Vg[rowbase + (long)(j0 + j) * D_ + dq];
            *(float4*)&KVs[j * 132 + dq] = v;
        }
        __syncthreads();

        // O += P @ V   (cols: tx*4..+3 and 64+tx*4..+3)
#pragma unroll 4
        for (int jj = 0; jj < 64; ++jj) {
            float4 pv = *(float4*)&Ps[jj * 68 + ty * 4];
            float4 v0 = *(float4*)&KVs[jj * 132 + tx * 4];
            float4 v1 = *(float4*)&KVs[jj * 132 + 64 + tx * 4];
            float pa[4] = {pv.x, pv.y, pv.z, pv.w};
            float va[8] = {v0.x, v0.y, v0.z, v0.w, v1.x, v1.y, v1.z, v1.w};
#pragma unroll
            for (int i = 0; i < 4; i++)
#pragma unroll
                for (int c = 0; c < 8; c++)
                    acc[i][c] += pa[i] * va[c];
        }
        __syncthreads();  // before next K overwrites KVs / Ps rewritten
    }

#pragma unroll
    for (int i = 0; i < 4; i++) {
        const float inv = 1.f / l[i];
        const long rb = rowbase + (long)(q0 + ty * 4 + i) * D_;
        *(float4*)&Og[rb + tx * 4] =
            make_float4(acc[i][0] * inv, acc[i][1] * inv, acc[i][2] * inv, acc[i][3] * inv);
        *(float4*)&Og[rb + 64 + tx * 4] =
            make_float4(acc[i][4] * inv, acc[i][5] * inv, acc[i][6] * inv, acc[i][7] * inv);
    }
}

// ---------------- launch ---------------------------------------------------
extern "C" void kernel_launch(void* const* d_in, const int* in_sizes, int n_in,
                              void* d_out, int out_size)
{
    const float* hidden   = (const float*)d_in[0];  // [2,2048,2048]
    const float* Wq_down  = (const float*)d_in[1];  // [1536,2048]
    const float* Wq_up    = (const float*)d_in[2];  // [2048,1536]
    const float* Wkv_down = (const float*)d_in[3];  // [512,2048]
    const float* k_up     = (const float*)d_in[4];  // [16,512,128]
    const float* v_up     = (const float*)d_in[5];  // [16,512,128]
    const float* Wo       = (const float*)d_in[6];  // [2048,2048]
    float* out = (float*)d_out;

    void* p;
    cudaGetSymbolAddress(&p, g_qdown); float* qdown = (float*)p;
    cudaGetSymbolAddress(&p, g_q);     float* q     = (float*)p;
    cudaGetSymbolAddress(&p, g_c);     float* c     = (float*)p;
    cudaGetSymbolAddress(&p, g_k);     float* k     = (float*)p;
    cudaGetSymbolAddress(&p, g_v);     float* v     = (float*)p;
    cudaGetSymbolAddress(&p, g_ao);    float* ao    = (float*)p;

    cudaFuncSetAttribute(attn_kernel,
                         cudaFuncAttributeMaxDynamicSharedMemorySize,
                         ATTN_SMEM_BYTES);

    const dim3 thr(256);

    // 1. qdown = hidden @ Wq_down^T     [4096,1536]
    gemm_kernel<true><<<dim3(RQ_ / BN, BL_ / BM), thr>>>(
        hidden, Wq_down, qdown, D_, D_, D_, RQ_, 0, 0);
    // 2. q = qdown @ Wq_up^T            [4096,2048]
    gemm_kernel<true><<<dim3(D_ / BN, BL_ / BM), thr>>>(
        qdown, Wq_up, q, RQ_, RQ_, RQ_, D_, 0, 0);
    // 3. c = hidden @ Wkv_down^T        [4096,512]
    gemm_kernel<true><<<dim3(RKV_ / BN, BL_ / BM), thr>>>(
        hidden, Wkv_down, c, D_, D_, D_, RKV_, 0, 0);
    // 4. k[:, h*128:+128] = c @ k_up[h]   (NN, batched over 16 heads)
    gemm_kernel<false><<<dim3(1, BL_ / BM, H_), thr>>>(
        c, k_up, k, RKV_, RKV_, HD_, D_, (long)RKV_ * HD_, (long)HD_);
    // 5. v likewise
    gemm_kernel<false><<<dim3(1, BL_ / BM, H_), thr>>>(
        c, v_up, v, RKV_, RKV_, HD_, D_, (long)RKV_ * HD_, (long)HD_);
    // 6. attention -> ao
    attn_kernel<<<dim3(L_ / 64, B_ * H_), thr, ATTN_SMEM_BYTES>>>(q, k, v, ao);
    // 7. out = ao @ Wo^T                [4096,2048]
    gemm_kernel<true><<<dim3(D_ / BN, BL_ / BM), thr>>>(
        ao, Wo, out, D_, D_, D_, D_, 0, 0);
}

// round 9
// speedup vs baseline: 1.5072x; 1.5072x over previous
#include <cuda_runtime.h>
#include <cuda_bf16.h>
#include <cstdint>

// Problem dims
#define B_    2
#define L_    2048
#define D_    2048
#define H_    16
#define HD_   128
#define RQ_   1536
#define RKV_  512
#define BL_   (B_ * L_)

#define SCALE_ 0.08838834764831845f  // 1/sqrt(128)

// ---------------- scratch (device globals; no allocation allowed) ----------
__device__ float g_qdown[BL_ * RQ_];   // [4096, 1536]
__device__ float g_q    [BL_ * D_];    // [4096, 2048]  q as [bs, h*128+d]
__device__ float g_c    [BL_ * RKV_];  // [4096, 512]
__device__ float g_k    [BL_ * D_];    // [4096, 2048]  k as [bs, h*128+d]
__device__ float g_v    [BL_ * D_];    // [4096, 2048]
__device__ float g_ao   [BL_ * D_];    // attention out, [bs, h*128+d]

// ---------------- split-bf16 tensor-core GEMM ------------------------------
// C[M,N] = A[M,K] * op(B), fp32 in/out, computed as
//   Ah*Bh + Ah*Bl + Al*Bh   with X = bf16(X) + bf16(X - bf16(X))
// NT=true : B is [N,K] row-major;  NT=false: B is [K,N] row-major.
// Block tile 128x128, BK=16. 8 warps, warp tile 64x32 (2x4 warp grid).
// mma.sync.aligned.m16n8k16.row.col.f32.bf16.bf16.f32
// smem: packed bf16x2 words, 8 words per row + 4 pad (stride 12 words)
//       -> fragment loads are bank-conflict-free ((g*12+tig) mod 32 distinct).

__device__ __forceinline__ void split_pack(float x, float y,
                                           uint32_t& hi, uint32_t& lo) {
    __nv_bfloat162 h = __floats2bfloat162_rn(x, y);
    float rx = x - __bfloat162float(h.x);
    float ry = y - __bfloat162float(h.y);
    __nv_bfloat162 l = __floats2bfloat162_rn(rx, ry);
    hi = reinterpret_cast<uint32_t&>(h);
    lo = reinterpret_cast<uint32_t&>(l);
}

__device__ __forceinline__ void mma_bf16(float* c, const uint32_t* a,
                                         const uint32_t* b) {
    asm("mma.sync.aligned.m16n8k16.row.col.f32.bf16.bf16.f32 "
        "{%0,%1,%2,%3}, {%4,%5,%6,%7}, {%8,%9}, {%0,%1,%2,%3};"
        : "+f"(c[0]), "+f"(c[1]), "+f"(c[2]), "+f"(c[3])
        : "r"(a[0]), "r"(a[1]), "r"(a[2]), "r"(a[3]), "r"(b[0]), "r"(b[1]));
}

#define SW 12   // smem row stride in 32-bit words (8 data + 4 pad)

template <bool NT>
__global__ __launch_bounds__(256, 2)
void gemm_tc(const float* __restrict__ A, const float* __restrict__ Bm,
             float* __restrict__ C, int K, int lda, int ldb, int ldc,
             long bStride, long cStride)
{
    __shared__ __align__(16) uint32_t Ah[128 * SW];
    __shared__ __align__(16) uint32_t Al[128 * SW];
    __shared__ __align__(16) uint32_t Bh[128 * SW];
    __shared__ __align__(16) uint32_t Bl[128 * SW];

    const int tid  = threadIdx.x;
    const int row0 = blockIdx.y * 128;
    const int col0 = blockIdx.x * 128;
    const float* Bp = Bm + (long)blockIdx.z * bStride;
    float*       Cp = C  + (long)blockIdx.z * cStride;

    // ---- loader indices ----
    // A (always [M,K]): 2 threads per 16-float row segment
    const int am  = tid >> 1;
    const int akf = (tid & 1) * 8;          // float offset in BK=16
    // B NT ([N,K]): same pattern.  B NN ([K,N]): k-pair x n-segment
    const int bn  = tid >> 1;               // NT
    const int kp  = tid >> 5;               // NN: k-pair 0..7
    const int nn  = (tid & 31) * 4;         // NN: n base

    // ---- compute indices ----
    const int lane = tid & 31, warp = tid >> 5;
    const int wm = warp & 1, wn = warp >> 1;
    const int g = lane >> 2, tig = lane & 3;
    const int aBase = (wm * 64 + g) * SW + tig;
    const int bBase = (wn * 32 + g) * SW + tig;

    float acc[4][4][4];
#pragma unroll
    for (int mi = 0; mi < 4; mi++)
#pragma unroll
        for (int ni = 0; ni < 4; ni++)
#pragma unroll
            for (int r = 0; r < 4; r++) acc[mi][ni][r] = 0.f;

    const int nt = K / 16;

    // prologue: prefetch tile 0
    float4 pa0 = *(const float4*)&A[(long)(row0 + am) * lda + akf];
    float4 pa1 = *(const float4*)&A[(long)(row0 + am) * lda + akf + 4];
    float4 pb0, pb1;
    if (NT) {
        pb0 = *(const float4*)&Bp[(long)(col0 + bn) * ldb + akf];
        pb1 = *(const float4*)&Bp[(long)(col0 + bn) * ldb + akf + 4];
    } else {
        pb0 = *(const float4*)&Bp[(long)(2 * kp    ) * ldb + col0 + nn];
        pb1 = *(const float4*)&Bp[(long)(2 * kp + 1) * ldb + col0 + nn];
    }

    for (int t = 0; t < nt; ++t) {
        // ---- store prefetched tile to smem (split hi/lo, pack bf16x2) ----
        {
            uint32_t wh[4], wl[4];
            split_pack(pa0.x, pa0.y, wh[0], wl[0]);
            split_pack(pa0.z, pa0.w, wh[1], wl[1]);
            split_pack(pa1.x, pa1.y, wh[2], wl[2]);
            split_pack(pa1.z, pa1.w, wh[3], wl[3]);
            const int off = am * SW + (tid & 1) * 4;
            *(uint4*)&Ah[off] = make_uint4(wh[0], wh[1], wh[2], wh[3]);
            *(uint4*)&Al[off] = make_uint4(wl[0], wl[1], wl[2], wl[3]);
        }
        if (NT) {
            uint32_t wh[4], wl[4];
            split_pack(pb0.x, pb0.y, wh[0], wl[0]);
            split_pack(pb0.z, pb0.w, wh[1], wl[1]);
            split_pack(pb1.x, pb1.y, wh[2], wl[2]);
            split_pack(pb1.z, pb1.w, wh[3], wl[3]);
            const int off = bn * SW + (tid & 1) * 4;
            *(uint4*)&Bh[off] = make_uint4(wh[0], wh[1], wh[2], wh[3]);
            *(uint4*)&Bl[off] = make_uint4(wl[0], wl[1], wl[2], wl[3]);
        } else {
            const float* f0 = &pb0.x;
            const float* f1 = &pb1.x;
#pragma unroll
            for (int j = 0; j < 4; j++) {
                uint32_t hw, lw;
                split_pack(f0[j], f1[j], hw, lw);   // low = even k
                Bh[(nn + j) * SW + kp] = hw;
                Bl[(nn + j) * SW + kp] = lw;
            }
        }
        __syncthreads();

        // ---- prefetch next tile (overlaps mma) ----
        if (t + 1 < nt) {
            const int k0 = (t + 1) * 16;
            pa0 = *(const float4*)&A[(long)(row0 + am) * lda + k0 + akf];
            pa1 = *(const float4*)&A[(long)(row0 + am) * lda + k0 + akf + 4];
            if (NT) {
                pb0 = *(const float4*)&Bp[(long)(col0 + bn) * ldb + k0 + akf];
                pb1 = *(const float4*)&Bp[(long)(col0 + bn) * ldb + k0 + akf + 4];
            } else {
                pb0 = *(const float4*)&Bp[(long)(k0 + 2 * kp    ) * ldb + col0 + nn];
                pb1 = *(const float4*)&Bp[(long)(k0 + 2 * kp + 1) * ldb + col0 + nn];
            }
        }

        // ---- tensor-core compute: 3-term split bf16 ----
        uint32_t bhf[4][2], blf[4][2];
#pragma unroll
        for (int ni = 0; ni < 4; ni++) {
            const int o = bBase + ni * (8 * SW);
            bhf[ni][0] = Bh[o]; bhf[ni][1] = Bh[o + 4];
            blf[ni][0] = Bl[o]; blf[ni][1] = Bl[o + 4];
        }
#pragma unroll
        for (int mi = 0; mi < 4; mi++) {
            const int o = aBase + mi * (16 * SW);
            uint32_t ah[4] = {Ah[o], Ah[o + 8 * SW], Ah[o + 4], Ah[o + 8 * SW + 4]};
#pragma unroll
            for (int ni = 0; ni < 4; ni++) mma_bf16(acc[mi][ni], ah, bhf[ni]);
#pragma unroll
            for (int ni = 0; ni < 4; ni++) mma_bf16(acc[mi][ni], ah, blf[ni]);
            uint32_t al[4] = {Al[o], Al[o + 8 * SW], Al[o + 4], Al[o + 8 * SW + 4]};
#pragma unroll
            for (int ni = 0; ni < 4; ni++) mma_bf16(acc[mi][ni], al, bhf[ni]);
        }
        __syncthreads();
    }

    // ---- epilogue ----
#pragma unroll
    for (int mi = 0; mi < 4; mi++) {
#pragma unroll
        for (int ni = 0; ni < 4; ni++) {
            const int row = row0 + wm * 64 + mi * 16 + g;
            const int col = col0 + wn * 32 + ni * 8 + tig * 2;
            float* p = Cp + (long)row * ldc + col;
            *(float2*)p = make_float2(acc[mi][ni][0], acc[mi][ni][1]);
            *(float2*)(p + 8L * ldc) = make_float2(acc[mi][ni][2], acc[mi][ni][3]);
        }
    }
}

// ---------------- flash attention (fp32, causal + ALiBi) -------------------
// grid: (L/64, B*H), 256 threads. BQ=64 queries, BK=64 key tile, d=128.
#define ATTN_SMEM_BYTES (20992 * 4)

__global__ __launch_bounds__(256, 2)
void attn_kernel(const float* __restrict__ Q, const float* __restrict__ Kg,
                 const float* __restrict__ Vg, float* __restrict__ Og)
{
    extern __shared__ float sm[];
    float* Qs  = sm;                  // [128][64]
    float* KVs = sm + 8192;           // K: [128][64] ; V: [64][132]
    float* Ps  = sm + 8192 + 8448;    // [64][68]

    const int tid = threadIdx.x;
    const int ty = tid >> 4;   // 0..15 -> q rows ty*4..ty*4+3
    const int tx = tid & 15;   // 0..15 -> keys tx*4..+3 / d-cols {tx*4, 64+tx*4}
    const int bh = blockIdx.y;
    const int b  = bh >> 4;
    const int h  = bh & 15;
    const int qt = blockIdx.x;
    const int q0 = qt * 64;
    const long rowbase = (long)b * L_ * D_ + (long)h * HD_;
    const float slope = exp2f(-0.5f * (float)(h + 1));

    // load Q tile transposed: Qs[dd][r]
#pragma unroll
    for (int it = 0; it < 8; ++it) {
        int fid = tid + it * 256;
        int r = fid & 63, dq = (fid >> 6) * 4;
        float4 v = *(const float4*)&Q[rowbase + (long)(q0 + r) * D_ + dq];
        Qs[(dq + 0) * 64 + r] = v.x;
        Qs[(dq + 1) * 64 + r] = v.y;
        Qs[(dq + 2) * 64 + r] = v.z;
        Qs[(dq + 3) * 64 + r] = v.w;
    }

    float m[4], l[4], acc[4][8];
#pragma unroll
    for (int i = 0; i < 4; i++) {
        m[i] = -1e30f; l[i] = 0.f;
#pragma unroll
        for (int c = 0; c < 8; c++) acc[i][c] = 0.f;
    }

    for (int kt = 0; kt <= qt; ++kt) {
        const int j0 = kt * 64;
        // load K tile transposed into KVs[dd][j]
#pragma unroll
        for (int it = 0; it < 8; ++it) {
            int fid = tid + it * 256;
            int r = fid & 63, dq = (fid >> 6) * 4;
            float4 v = *(const float4*)&Kg[rowbase + (long)(j0 + r) * D_ + dq];
            KVs[(dq + 0) * 64 + r] = v.x;
            KVs[(dq + 1) * 64 + r] = v.y;
            KVs[(dq + 2) * 64 + r] = v.z;
            KVs[(dq + 3) * 64 + r] = v.w;
        }
        __syncthreads();   // also guards Qs on first iteration

        // scores: S[4q][4k] over d=128
        float s[4][4];
#pragma unroll
        for (int i = 0; i < 4; i++)
#pragma unroll
            for (int j = 0; j < 4; j++) s[i][j] = 0.f;

#pragma unroll 4
        for (int dd = 0; dd < 128; ++dd) {
            float4 qv = *(float4*)&Qs[dd * 64 + ty * 4];
            float4 kv = *(float4*)&KVs[dd * 64 + tx * 4];
            float qa[4] = {qv.x, qv.y, qv.z, qv.w};
            float ka[4] = {kv.x, kv.y, kv.z, kv.w};
#pragma unroll
            for (int i = 0; i < 4; i++)
#pragma unroll
                for (int j = 0; j < 4; j++)
                    s[i][j] += qa[i] * ka[j];
        }
        __syncthreads();  // done reading KVs (K)

        const bool diag = (kt == qt);
        float alpha[4];
#pragma unroll
        for (int i = 0; i < 4; i++) {
            const int ig = q0 + ty * 4 + i;
            float sv[4];
            float tmax = -1e30f;
#pragma unroll
            for (int j = 0; j < 4; j++) {
                const int jg = j0 + tx * 4 + j;
                float val = s[i][j] * SCALE_ - slope * (float)(ig - jg);
                if (diag && jg > ig) val = -1e30f;
                sv[j] = val;
                tmax = fmaxf(tmax, val);
            }
#pragma unroll
            for (int off = 1; off < 16; off <<= 1)
                tmax = fmaxf(tmax, __shfl_xor_sync(0xffffffffu, tmax, off));
            const float mn = fmaxf(m[i], tmax);
            alpha[i] = __expf(m[i] - mn);
            float ts = 0.f;
#pragma unroll
            for (int j = 0; j < 4; j++) {
                const float p = __expf(sv[j] - mn);
                ts += p;
                Ps[(tx * 4 + j) * 68 + ty * 4 + i] = p;   // transposed stage
            }
#pragma unroll
            for (int off = 1; off < 16; off <<= 1)
                ts += __shfl_xor_sync(0xffffffffu, ts, off);
            l[i] = l[i] * alpha[i] + ts;
            m[i] = mn;
#pragma unroll
            for (int c = 0; c < 8; c++) acc[i][c] *= alpha[i];
        }

        // load V tile (direct) into KVs[j][dd], stride 132
#pragma unroll
        for (int it = 0; it < 8; ++it) {
            int fid = tid + it * 256;
            int j = fid >> 5, dq = (fid & 31) * 4;
            float4 v = *(const float4*)&Vg[rowbase + (long)(j0 + j) * D_ + dq];
            *(float4*)&KVs[j * 132 + dq] = v;
        }
        __syncthreads();

        // O += P @ V   (cols: tx*4..+3 and 64+tx*4..+3)
#pragma unroll 4
        for (int jj = 0; jj < 64; ++jj) {
            float4 pv = *(float4*)&Ps[jj * 68 + ty * 4];
            float4 v0 = *(float4*)&KVs[jj * 132 + tx * 4];
            float4 v1 = *(float4*)&KVs[jj * 132 + 64 + tx * 4];
            float pa[4] = {pv.x, pv.y, pv.z, pv.w};
            float va[8] = {v0.x, v0.y, v0.z, v0.w, v1.x, v1.y, v1.z, v1.w};
#pragma unroll
            for (int i = 0; i < 4; i++)
#pragma unroll
                for (int c = 0; c < 8; c++)
                    acc[i][c] += pa[i] * va[c];
        }
        __syncthreads();  // before next K overwrites KVs / Ps rewritten
    }

#pragma unroll
    for (int i = 0; i < 4; i++) {
        const float inv = 1.f / l[i];
        const long rb = rowbase + (long)(q0 + ty * 4 + i) * D_;
        *(float4*)&Og[rb + tx * 4] =
            make_float4(acc[i][0] * inv, acc[i][1] * inv, acc[i][2] * inv, acc[i][3] * inv);
        *(float4*)&Og[rb + 64 + tx * 4] =
            make_float4(acc[i][4] * inv, acc[i][5] * inv, acc[i][6] * inv, acc[i][7] * inv);
    }
}

// ---------------- launch ---------------------------------------------------
extern "C" void kernel_launch(void* const* d_in, const int* in_sizes, int n_in,
                              void* d_out, int out_size)
{
    const float* hidden   = (const float*)d_in[0];  // [2,2048,2048]
    const float* Wq_down  = (const float*)d_in[1];  // [1536,2048]
    const float* Wq_up    = (const float*)d_in[2];  // [2048,1536]
    const float* Wkv_down = (const float*)d_in[3];  // [512,2048]
    const float* k_up     = (const float*)d_in[4];  // [16,512,128]
    const float* v_up     = (const float*)d_in[5];  // [16,512,128]
    const float* Wo       = (const float*)d_in[6];  // [2048,2048]
    float* out = (float*)d_out;

    void* p;
    cudaGetSymbolAddress(&p, g_qdown); float* qdown = (float*)p;
    cudaGetSymbolAddress(&p, g_q);     float* q     = (float*)p;
    cudaGetSymbolAddress(&p, g_c);     float* c     = (float*)p;
    cudaGetSymbolAddress(&p, g_k);     float* k     = (float*)p;
    cudaGetSymbolAddress(&p, g_v);     float* v     = (float*)p;
    cudaGetSymbolAddress(&p, g_ao);    float* ao    = (float*)p;

    cudaFuncSetAttribute(attn_kernel,
                         cudaFuncAttributeMaxDynamicSharedMemorySize,
                         ATTN_SMEM_BYTES);

    const dim3 thr(256);

    // 1. qdown = hidden @ Wq_down^T     [4096,1536]
    gemm_tc<true><<<dim3(RQ_ / 128, BL_ / 128), thr>>>(
        hidden, Wq_down, qdown, D_, D_, D_, RQ_, 0, 0);
    // 2. q = qdown @ Wq_up^T            [4096,2048]
    gemm_tc<true><<<dim3(D_ / 128, BL_ / 128), thr>>>(
        qdown, Wq_up, q, RQ_, RQ_, RQ_, D_, 0, 0);
    // 3. c = hidden @ Wkv_down^T        [4096,512]
    gemm_tc<true><<<dim3(RKV_ / 128, BL_ / 128), thr>>>(
        hidden, Wkv_down, c, D_, D_, D_, RKV_, 0, 0);
    // 4. k[:, h*128:+128] = c @ k_up[h]   (NN, batched over 16 heads)
    gemm_tc<false><<<dim3(1, BL_ / 128, H_), thr>>>(
        c, k_up, k, RKV_, RKV_, HD_, D_, (long)RKV_ * HD_, (long)HD_);
    // 5. v likewise
    gemm_tc<false><<<dim3(1, BL_ / 128, H_), thr>>>(
        c, v_up, v, RKV_, RKV_, HD_, D_, (long)RKV_ * HD_, (long)HD_);
    // 6. attention -> ao
    attn_kernel<<<dim3(L_ / 64, B_ * H_), thr, ATTN_SMEM_BYTES>>>(q, k, v, ao);
    // 7. out = ao @ Wo^T                [4096,2048]
    gemm_tc<true><<<dim3(D_ / 128, BL_ / 128), thr>>>(
        ao, Wo, out, D_, D_, D_, D_, 0, 0);
}

// round 10
// speedup vs baseline: 2.0930x; 1.3887x over previous
#include <cuda_runtime.h>
#include <cuda_bf16.h>
#include <cstdint>

// Problem dims
#define B_    2
#define L_    2048
#define D_    2048
#define H_    16
#define HD_   128
#define RQ_   1536
#define RKV_  512
#define BL_   (B_ * L_)

#define SCALE_ 0.08838834764831845f  // 1/sqrt(128)

// ---------------- scratch (device globals; no allocation allowed) ----------
__device__ float g_qdown[BL_ * RQ_];
__device__ float g_q    [BL_ * D_];
__device__ float g_c    [BL_ * RKV_];
__device__ float g_k    [BL_ * D_];
__device__ float g_v    [BL_ * D_];
__device__ float g_ao   [BL_ * D_];

// packed split-bf16 operands for attention (uint32 = bf16x2 words)
// Q/K: [bh][2048][64 words] (d-pairs, 8-group permuted)
// V  : [bh][128][1024 words] (l-pairs, 8-group permuted), i.e. V transposed
#define QK_WORDS (32 * 2048 * 64)
#define V_WORDS  (32 * 128 * 1024)
__device__ uint32_t g_Qh[QK_WORDS], g_Ql[QK_WORDS];
__device__ uint32_t g_Kh[QK_WORDS], g_Kl[QK_WORDS];
__device__ uint32_t g_Vh[V_WORDS],  g_Vl[V_WORDS];

// ---------------- helpers --------------------------------------------------
__device__ __forceinline__ void split_pack(float x, float y,
                                           uint32_t& hi, uint32_t& lo) {
    __nv_bfloat162 h = __floats2bfloat162_rn(x, y);
    float rx = x - __bfloat162float(h.x);
    float ry = y - __bfloat162float(h.y);
    __nv_bfloat162 l = __floats2bfloat162_rn(rx, ry);
    hi = reinterpret_cast<uint32_t&>(h);
    lo = reinterpret_cast<uint32_t&>(l);
}

__device__ __forceinline__ void mma_bf16(float* c, const uint32_t* a,
                                         const uint32_t* b) {
    asm("mma.sync.aligned.m16n8k16.row.col.f32.bf16.bf16.f32 "
        "{%0,%1,%2,%3}, {%4,%5,%6,%7}, {%8,%9}, {%0,%1,%2,%3};"
        : "+f"(c[0]), "+f"(c[1]), "+f"(c[2]), "+f"(c[3])
        : "r"(a[0]), "r"(a[1]), "r"(a[2]), "r"(a[3]), "r"(b[0]), "r"(b[1]));
}

// in-8-group word permutation: natural pair-index i -> fragment-friendly pos
__device__ __forceinline__ int perm8(int w) {
    return (w & ~7) | (((w & 3) << 1) | ((w >> 2) & 1));
}

// ---------------- split-bf16 tensor-core GEMM (unchanged) ------------------
#define SW 12

template <bool NT>
__global__ __launch_bounds__(256, 2)
void gemm_tc(const float* __restrict__ A, const float* __restrict__ Bm,
             float* __restrict__ C, int K, int lda, int ldb, int ldc,
             long bStride, long cStride)
{
    __shared__ __align__(16) uint32_t Ah[128 * SW];
    __shared__ __align__(16) uint32_t Al[128 * SW];
    __shared__ __align__(16) uint32_t Bh[128 * SW];
    __shared__ __align__(16) uint32_t Bl[128 * SW];

    const int tid  = threadIdx.x;
    const int row0 = blockIdx.y * 128;
    const int col0 = blockIdx.x * 128;
    const float* Bp = Bm + (long)blockIdx.z * bStride;
    float*       Cp = C  + (long)blockIdx.z * cStride;

    const int am  = tid >> 1;
    const int akf = (tid & 1) * 8;
    const int bn  = tid >> 1;
    const int kp  = tid >> 5;
    const int nn  = (tid & 31) * 4;

    const int lane = tid & 31, warp = tid >> 5;
    const int wm = warp & 1, wn = warp >> 1;
    const int g = lane >> 2, tig = lane & 3;
    const int aBase = (wm * 64 + g) * SW + tig;
    const int bBase = (wn * 32 + g) * SW + tig;

    float acc[4][4][4];
#pragma unroll
    for (int mi = 0; mi < 4; mi++)
#pragma unroll
        for (int ni = 0; ni < 4; ni++)
#pragma unroll
            for (int r = 0; r < 4; r++) acc[mi][ni][r] = 0.f;

    const int nt = K / 16;

    float4 pa0 = *(const float4*)&A[(long)(row0 + am) * lda + akf];
    float4 pa1 = *(const float4*)&A[(long)(row0 + am) * lda + akf + 4];
    float4 pb0, pb1;
    if (NT) {
        pb0 = *(const float4*)&Bp[(long)(col0 + bn) * ldb + akf];
        pb1 = *(const float4*)&Bp[(long)(col0 + bn) * ldb + akf + 4];
    } else {
        pb0 = *(const float4*)&Bp[(long)(2 * kp    ) * ldb + col0 + nn];
        pb1 = *(const float4*)&Bp[(long)(2 * kp + 1) * ldb + col0 + nn];
    }

    for (int t = 0; t < nt; ++t) {
        {
            uint32_t wh[4], wl[4];
            split_pack(pa0.x, pa0.y, wh[0], wl[0]);
            split_pack(pa0.z, pa0.w, wh[1], wl[1]);
            split_pack(pa1.x, pa1.y, wh[2], wl[2]);
            split_pack(pa1.z, pa1.w, wh[3], wl[3]);
            const int off = am * SW + (tid & 1) * 4;
            *(uint4*)&Ah[off] = make_uint4(wh[0], wh[1], wh[2], wh[3]);
            *(uint4*)&Al[off] = make_uint4(wl[0], wl[1], wl[2], wl[3]);
        }
        if (NT) {
            uint32_t wh[4], wl[4];
            split_pack(pb0.x, pb0.y, wh[0], wl[0]);
            split_pack(pb0.z, pb0.w, wh[1], wl[1]);
            split_pack(pb1.x, pb1.y, wh[2], wl[2]);
            split_pack(pb1.z, pb1.w, wh[3], wl[3]);
            const int off = bn * SW + (tid & 1) * 4;
            *(uint4*)&Bh[off] = make_uint4(wh[0], wh[1], wh[2], wh[3]);
            *(uint4*)&Bl[off] = make_uint4(wl[0], wl[1], wl[2], wl[3]);
        } else {
            const float* f0 = &pb0.x;
            const float* f1 = &pb1.x;
#pragma unroll
            for (int j = 0; j < 4; j++) {
                uint32_t hw, lw;
                split_pack(f0[j], f1[j], hw, lw);
                Bh[(nn + j) * SW + kp] = hw;
                Bl[(nn + j) * SW + kp] = lw;
            }
        }
        __syncthreads();

        if (t + 1 < nt) {
            const int k0 = (t + 1) * 16;
            pa0 = *(const float4*)&A[(long)(row0 + am) * lda + k0 + akf];
            pa1 = *(const float4*)&A[(long)(row0 + am) * lda + k0 + akf + 4];
            if (NT) {
                pb0 = *(const float4*)&Bp[(long)(col0 + bn) * ldb + k0 + akf];
                pb1 = *(const float4*)&Bp[(long)(col0 + bn) * ldb + k0 + akf + 4];
            } else {
                pb0 = *(const float4*)&Bp[(long)(k0 + 2 * kp    ) * ldb + col0 + nn];
                pb1 = *(const float4*)&Bp[(long)(k0 + 2 * kp + 1) * ldb + col0 + nn];
            }
        }

        uint32_t bhf[4][2], blf[4][2];
#pragma unroll
        for (int ni = 0; ni < 4; ni++) {
            const int o = bBase + ni * (8 * SW);
            bhf[ni][0] = Bh[o]; bhf[ni][1] = Bh[o + 4];
            blf[ni][0] = Bl[o]; blf[ni][1] = Bl[o + 4];
        }
#pragma unroll
        for (int mi = 0; mi < 4; mi++) {
            const int o = aBase + mi * (16 * SW);
            uint32_t ah[4] = {Ah[o], Ah[o + 8 * SW], Ah[o + 4], Ah[o + 8 * SW + 4]};
#pragma unroll
            for (int ni = 0; ni < 4; ni++) mma_bf16(acc[mi][ni], ah, bhf[ni]);
#pragma unroll
            for (int ni = 0; ni < 4; ni++) mma_bf16(acc[mi][ni], ah, blf[ni]);
            uint32_t al[4] = {Al[o], Al[o + 8 * SW], Al[o + 4], Al[o + 8 * SW + 4]};
#pragma unroll
            for (int ni = 0; ni < 4; ni++) mma_bf16(acc[mi][ni], al, bhf[ni]);
        }
        __syncthreads();
    }

#pragma unroll
    for (int mi = 0; mi < 4; mi++) {
#pragma unroll
        for (int ni = 0; ni < 4; ni++) {
            const int row = row0 + wm * 64 + mi * 16 + g;
            const int col = col0 + wn * 32 + ni * 8 + tig * 2;
            float* p = Cp + (long)row * ldc + col;
            *(float2*)p = make_float2(acc[mi][ni][0], acc[mi][ni][1]);
            *(float2*)(p + 8L * ldc) = make_float2(acc[mi][ni][2], acc[mi][ni][3]);
        }
    }
}

// ---------------- pack Q/K into split-bf16 mma layout ----------------------
// word (bh, l, wk): floats (2wk, 2wk+1) of head-row -> permuted word
__global__ __launch_bounds__(256)
void pack_qk(const float* __restrict__ Q, const float* __restrict__ K,
             uint32_t* __restrict__ Qh, uint32_t* __restrict__ Ql,
             uint32_t* __restrict__ Kh, uint32_t* __restrict__ Kl)
{
    const long idx = (long)blockIdx.x * 256 + threadIdx.x;  // 0..2*4194304-1
    const int tensor = (int)(idx >> 22);
    const int rem = (int)(idx & 4194303);
    const int bh = rem >> 17;
    const int rem2 = rem & 131071;
    const int l = rem2 >> 6, wk = rem2 & 63;
    const int b = bh >> 4, h = bh & 15;
    const float* src = (tensor ? K : Q)
        + ((long)(b * L_ + l)) * D_ + h * HD_ + wk * 2;
    float2 f = *(const float2*)src;
    uint32_t hi, lo;
    split_pack(f.x, f.y, hi, lo);
    const long dsti = (long)bh * 131072 + l * 64 + perm8(wk);
    if (tensor) { Kh[dsti] = hi; Kl[dsti] = lo; }
    else        { Qh[dsti] = hi; Ql[dsti] = lo; }
}

// ---------------- pack V: transpose + split --------------------------------
// out word (bh, d, lw): V[2lw][d], V[2lw+1][d]
__global__ __launch_bounds__(256)
void pack_v(const float* __restrict__ V,
            uint32_t* __restrict__ Vh, uint32_t* __restrict__ Vl)
{
    __shared__ float vs[64][65];
    const int tid = threadIdx.x;
    const int l0 = blockIdx.x * 64, d0 = blockIdx.y * 64;
    const int bh = blockIdx.z, b = bh >> 4, h = bh & 15;
#pragma unroll
    for (int it = 0; it < 4; ++it) {
        int fid = tid + it * 256;             // 0..1023 float4 slots
        int l = fid >> 4, part = fid & 15;
        float4 f = *(const float4*)&V[((long)(b * L_ + l0 + l)) * D_
                                      + h * HD_ + d0 + part * 4];
        vs[l][part * 4 + 0] = f.x; vs[l][part * 4 + 1] = f.y;
        vs[l][part * 4 + 2] = f.z; vs[l][part * 4 + 3] = f.w;
    }
    __syncthreads();
#pragma unroll
    for (int it = 0; it < 8; ++it) {
        int wi = tid + it * 256;              // 0..2047
        int d = wi >> 5, lw = wi & 31;
        uint32_t hi, lo;
        split_pack(vs[2 * lw][d], vs[2 * lw + 1][d], hi, lo);
        const long dsti = (long)bh * 131072 + (long)(d0 + d) * 1024
                          + (l0 >> 1) + perm8(lw);
        Vh[dsti] = hi; Vl[dsti] = lo;
    }
}

// ---------------- tensor-core flash attention ------------------------------
// grid (L/64, B*H), 256 thr. 8 warps: wm=warp&3 (16 S-rows), wn=warp>>2
// (32 S-cols / 32 j of PV). Q/K/V split-bf16, 3-term mma. O frags in regs.
// smem words: QsH 4608 | QsL 4608 | KV buf 10240 | red 256 = 19712 (78848 B)
#define AT_QS_ST 72
#define AT_VS_ST 40
#define AT_SMEM_BYTES (19712 * 4)

__global__ __launch_bounds__(256, 2)
void attn_tc(const uint32_t* __restrict__ Qh, const uint32_t* __restrict__ Ql,
             const uint32_t* __restrict__ Kh, const uint32_t* __restrict__ Kl,
             const uint32_t* __restrict__ Vh, const uint32_t* __restrict__ Vl,
             float* __restrict__ Og)
{
    extern __shared__ uint32_t sw[];
    uint32_t* QsH = sw;                 // 64 x 72
    uint32_t* QsL = sw + 4608;
    uint32_t* KsH = sw + 9216;          // 64 x 72
    uint32_t* KsL = sw + 13824;
    uint32_t* VsH = sw + 9216;          // 128 x 40 (shares buffer with Ks)
    uint32_t* VsL = sw + 14336;
    float* redA = (float*)(sw + 19456); // [2][64]
    float* redB = (float*)(sw + 19584); // [2][64]
    float* Ost  = (float*)(sw + 9216);  // 64 x 132 (reuses KV buffer)

    const int tid = threadIdx.x;
    const int lane = tid & 31, warp = tid >> 5;
    const int wm = warp & 3, wn = warp >> 2;
    const int g = lane >> 2, tig = lane & 3;
    const int bh = blockIdx.y;
    const int b = bh >> 4, h = bh & 15;
    const int qt = gridDim.x - 1 - blockIdx.x;   // heavy tiles first
    const int q0 = qt * 64;
    const float slope = exp2f(-0.5f * (float)(h + 1));
    const long qkbase = (long)bh * 131072;
    const long vbase  = (long)bh * 131072;
    const int rowA = wm * 16 + g;

    // load Q tile (both arrays), 8 uint4 per thread
#pragma unroll
    for (int it = 0; it < 8; ++it) {
        int fid = tid + it * 256;
        int arr = fid >> 10, rem = fid & 1023;
        int r = rem >> 4, part = rem & 15;
        const uint32_t* src = (arr ? Ql : Qh) + qkbase + (long)(q0 + r) * 64 + part * 4;
        uint32_t* dst = (arr ? QsL : QsH) + r * AT_QS_ST + part * 4;
        *(uint4*)dst = *(const uint4*)src;
    }
    // load K tile 0
#pragma unroll
    for (int it = 0; it < 8; ++it) {
        int fid = tid + it * 256;
        int arr = fid >> 10, rem = fid & 1023;
        int r = rem >> 4, part = rem & 15;
        const uint32_t* src = (arr ? Kl : Kh) + qkbase + (long)r * 64 + part * 4;
        uint32_t* dst = (arr ? KsL : KsH) + r * AT_QS_ST + part * 4;
        *(uint4*)dst = *(const uint4*)src;
    }
    __syncthreads();

    float m0 = -1e30f, m1 = -1e30f, l0 = 0.f, l1 = 0.f;
    float o[16][4];
#pragma unroll
    for (int ni = 0; ni < 16; ni++)
#pragma unroll
        for (int r = 0; r < 4; r++) o[ni][r] = 0.f;

    for (int kt = 0; kt <= qt; ++kt) {
        const int j0 = kt * 64;

        // ---- S = Q K^T (3-term split) ----
        float s[4][4];
#pragma unroll
        for (int ni = 0; ni < 4; ni++)
#pragma unroll
            for (int r = 0; r < 4; r++) s[ni][r] = 0.f;

#pragma unroll
        for (int kc = 0; kc < 8; ++kc) {
            const int ao_ = rowA * AT_QS_ST + kc * 8 + 2 * tig;
            uint2 qh0 = *(uint2*)&QsH[ao_];
            uint2 qh1 = *(uint2*)&QsH[ao_ + 8 * AT_QS_ST];
            uint2 ql0 = *(uint2*)&QsL[ao_];
            uint2 ql1 = *(uint2*)&QsL[ao_ + 8 * AT_QS_ST];
            uint32_t ah[4] = {qh0.x, qh1.x, qh0.y, qh1.y};
            uint32_t al[4] = {ql0.x, ql1.x, ql0.y, ql1.y};
#pragma unroll
            for (int ni = 0; ni < 4; ++ni) {
                const int bo = (wn * 32 + ni * 8 + g) * AT_QS_ST + kc * 8 + 2 * tig;
                uint2 kh2 = *(uint2*)&KsH[bo];
                uint2 kl2 = *(uint2*)&KsL[bo];
                uint32_t bhp[2] = {kh2.x, kh2.y};
                uint32_t blp[2] = {kl2.x, kl2.y};
                mma_bf16(s[ni], ah, bhp);
                mma_bf16(s[ni], ah, blp);
                mma_bf16(s[ni], al, bhp);
            }
        }

        // ---- scale + alibi + mask, partial row max ----
        const bool diag = (kt == qt);
        float mx0 = -1e30f, mx1 = -1e30f;
#pragma unroll
        for (int ni = 0; ni < 4; ++ni) {
#pragma unroll
            for (int r = 0; r < 4; ++r) {
                const int ig = q0 + rowA + ((r >= 2) ? 8 : 0);
                const int jg = j0 + wn * 32 + ni * 8 + 2 * tig + (r & 1);
                float val = s[ni][r] * SCALE_ - slope * (float)(ig - jg);
                if (diag && jg > ig) val = -1e30f;
                s[ni][r] = val;
                if (r < 2) mx0 = fmaxf(mx0, val); else mx1 = fmaxf(mx1, val);
            }
        }
        mx0 = fmaxf(mx0, __shfl_xor_sync(0xffffffffu, mx0, 1));
        mx0 = fmaxf(mx0, __shfl_xor_sync(0xffffffffu, mx0, 2));
        mx1 = fmaxf(mx1, __shfl_xor_sync(0xffffffffu, mx1, 1));
        mx1 = fmaxf(mx1, __shfl_xor_sync(0xffffffffu, mx1, 2));
        if (tig == 0) {
            redA[wn * 64 + rowA] = mx0;
            redA[wn * 64 + rowA + 8] = mx1;
        }
        __syncthreads();

        // ---- V tile copy (into shared KV buffer; S-phase done) ----
#pragma unroll
        for (int it = 0; it < 8; ++it) {
            int fid = tid + it * 256;
            int arr = fid >> 10, rem = fid & 1023;
            int d = rem >> 3, part = rem & 7;
            const uint32_t* src = (arr ? Vl : Vh) + vbase + (long)d * 1024
                                  + (j0 >> 1) + part * 4;
            uint32_t* dst = (arr ? VsL : VsH) + d * AT_VS_ST + part * 4;
            *(uint4*)dst = *(const uint4*)src;
        }

        // ---- exp + partial row sum ----
        const float mn0 = fmaxf(m0, fmaxf(redA[rowA], redA[64 + rowA]));
        const float mn1 = fmaxf(m1, fmaxf(redA[rowA + 8], redA[64 + rowA + 8]));
        float ps0 = 0.f, ps1 = 0.f;
#pragma unroll
        for (int ni = 0; ni < 4; ++ni) {
#pragma unroll
            for (int r = 0; r < 4; ++r) {
                float p = __expf(s[ni][r] - ((r < 2) ? mn0 : mn1));
                s[ni][r] = p;
                if (r < 2) ps0 += p; else ps1 += p;
            }
        }
        ps0 += __shfl_xor_sync(0xffffffffu, ps0, 1);
        ps0 += __shfl_xor_sync(0xffffffffu, ps0, 2);
        ps1 += __shfl_xor_sync(0xffffffffu, ps1, 1);
        ps1 += __shfl_xor_sync(0xffffffffu, ps1, 2);
        if (tig == 0) {
            redB[wn * 64 + rowA] = ps0;
            redB[wn * 64 + rowA + 8] = ps1;
        }
        __syncthreads();

        // ---- online-softmax state update + O rescale ----
        const float alpha0 = __expf(m0 - mn0);
        const float alpha1 = __expf(m1 - mn1);
        l0 = l0 * alpha0 + redB[rowA] + redB[64 + rowA];
        l1 = l1 * alpha1 + redB[rowA + 8] + redB[64 + rowA + 8];
        m0 = mn0; m1 = mn1;
#pragma unroll
        for (int ni = 0; ni < 16; ++ni) {
            o[ni][0] *= alpha0; o[ni][1] *= alpha0;
            o[ni][2] *= alpha1; o[ni][3] *= alpha1;
        }

        // ---- pack P frags and PV mma (3-term split) ----
        uint32_t ph[4][2], pl[4][2];
#pragma unroll
        for (int ni = 0; ni < 4; ++ni) {
            split_pack(s[ni][0], s[ni][1], ph[ni][0], pl[ni][0]);
            split_pack(s[ni][2], s[ni][3], ph[ni][1], pl[ni][1]);
        }
#pragma unroll
        for (int jcl = 0; jcl < 2; ++jcl) {
            uint32_t pah[4] = {ph[2 * jcl][0], ph[2 * jcl][1],
                               ph[2 * jcl + 1][0], ph[2 * jcl + 1][1]};
            uint32_t pal[4] = {pl[2 * jcl][0], pl[2 * jcl][1],
                               pl[2 * jcl + 1][0], pl[2 * jcl + 1][1]};
#pragma unroll
            for (int ni = 0; ni < 16; ++ni) {
                const int vo = (ni * 8 + g) * AT_VS_ST + wn * 16 + jcl * 8 + 2 * tig;
                uint2 vh2 = *(uint2*)&VsH[vo];
                uint2 vl2 = *(uint2*)&VsL[vo];
                uint32_t vbh[2] = {vh2.x, vh2.y};
                uint32_t vbl[2] = {vl2.x, vl2.y};
                mma_bf16(o[ni], pah, vbh);
                mma_bf16(o[ni], pah, vbl);
                mma_bf16(o[ni], pal, vbh);
            }
        }
        __syncthreads();

        // ---- next K tile ----
        if (kt < qt) {
            const int jn = (kt + 1) * 64;
#pragma unroll
            for (int it = 0; it < 8; ++it) {
                int fid = tid + it * 256;
                int arr = fid >> 10, rem = fid & 1023;
                int r = rem >> 4, part = rem & 15;
                const uint32_t* src = (arr ? Kl : Kh) + qkbase
                                      + (long)(jn + r) * 64 + part * 4;
                uint32_t* dst = (arr ? KsL : KsH) + r * AT_QS_ST + part * 4;
                *(uint4*)dst = *(const uint4*)src;
            }
            __syncthreads();
        }
    }

    // ---- combine wn halves, normalize, store ----
    __syncthreads();
    if (wn == 1) {
#pragma unroll
        for (int ni = 0; ni < 16; ++ni) {
            const int col = ni * 8 + 2 * tig;
            *(float2*)&Ost[rowA * 132 + col] = make_float2(o[ni][0], o[ni][1]);
            *(float2*)&Ost[(rowA + 8) * 132 + col] = make_float2(o[ni][2], o[ni][3]);
        }
    }
    __syncthreads();
    if (wn == 0) {
        const float inv0 = 1.f / l0, inv1 = 1.f / l1;
        const long rb0 = ((long)(b * L_ + q0 + rowA)) * D_ + h * HD_;
        const long rb1 = ((long)(b * L_ + q0 + rowA + 8)) * D_ + h * HD_;
#pragma unroll
        for (int ni = 0; ni < 16; ++ni) {
            const int col = ni * 8 + 2 * tig;
            float2 a0 = *(float2*)&Ost[rowA * 132 + col];
            float2 a1 = *(float2*)&Ost[(rowA + 8) * 132 + col];
            *(float2*)&Og[rb0 + col] =
                make_float2((o[ni][0] + a0.x) * inv0, (o[ni][1] + a0.y) * inv0);
            *(float2*)&Og[rb1 + col] =
                make_float2((o[ni][2] + a1.x) * inv1, (o[ni][3] + a1.y) * inv1);
        }
    }
}

// ---------------- launch ---------------------------------------------------
extern "C" void kernel_launch(void* const* d_in, const int* in_sizes, int n_in,
                              void* d_out, int out_size)
{
    const float* hidden   = (const float*)d_in[0];
    const float* Wq_down  = (const float*)d_in[1];
    const float* Wq_up    = (const float*)d_in[2];
    const float* Wkv_down = (const float*)d_in[3];
    const float* k_up     = (const float*)d_in[4];
    const float* v_up     = (const float*)d_in[5];
    const float* Wo       = (const float*)d_in[6];
    float* out = (float*)d_out;

    void* p;
    cudaGetSymbolAddress(&p, g_qdown); float* qdown = (float*)p;
    cudaGetSymbolAddress(&p, g_q);     float* q     = (float*)p;
    cudaGetSymbolAddress(&p, g_c);     float* c     = (float*)p;
    cudaGetSymbolAddress(&p, g_k);     float* k     = (float*)p;
    cudaGetSymbolAddress(&p, g_v);     float* v     = (float*)p;
    cudaGetSymbolAddress(&p, g_ao);    float* ao    = (float*)p;
    cudaGetSymbolAddress(&p, g_Qh); uint32_t* Qh = (uint32_t*)p;
    cudaGetSymbolAddress(&p, g_Ql); uint32_t* Ql = (uint32_t*)p;
    cudaGetSymbolAddress(&p, g_Kh); uint32_t* Kh = (uint32_t*)p;
    cudaGetSymbolAddress(&p, g_Kl); uint32_t* Kl = (uint32_t*)p;
    cudaGetSymbolAddress(&p, g_Vh); uint32_t* Vh = (uint32_t*)p;
    cudaGetSymbolAddress(&p, g_Vl); uint32_t* Vl = (uint32_t*)p;

    cudaFuncSetAttribute(attn_tc,
                         cudaFuncAttributeMaxDynamicSharedMemorySize,
                         AT_SMEM_BYTES);

    const dim3 thr(256);

    // 1. qdown = hidden @ Wq_down^T
    gemm_tc<true><<<dim3(RQ_ / 128, BL_ / 128), thr>>>(
        hidden, Wq_down, qdown, D_, D_, D_, RQ_, 0, 0);
    // 2. q = qdown @ Wq_up^T
    gemm_tc<true><<<dim3(D_ / 128, BL_ / 128), thr>>>(
        qdown, Wq_up, q, RQ_, RQ_, RQ_, D_, 0, 0);
    // 3. c = hidden @ Wkv_down^T
    gemm_tc<true><<<dim3(RKV_ / 128, BL_ / 128), thr>>>(
        hidden, Wkv_down, c, D_, D_, D_, RKV_, 0, 0);
    // 4. k per head
    gemm_tc<false><<<dim3(1, BL_ / 128, H_), thr>>>(
        c, k_up, k, RKV_, RKV_, HD_, D_, (long)RKV_ * HD_, (long)HD_);
    // 5. v per head
    gemm_tc<false><<<dim3(1, BL_ / 128, H_), thr>>>(
        c, v_up, v, RKV_, RKV_, HD_, D_, (long)RKV_ * HD_, (long)HD_);
    // 6. pack q/k/v into split-bf16 mma layouts
    pack_qk<<<32768, thr>>>(q, k, Qh, Ql, Kh, Kl);
    pack_v<<<dim3(L_ / 64, HD_ / 64, B_ * H_), thr>>>(v, Vh, Vl);
    // 7. attention -> ao
    attn_tc<<<dim3(L_ / 64, B_ * H_), thr, AT_SMEM_BYTES>>>(
        Qh, Ql, Kh, Kl, Vh, Vl, ao);
    // 8. out = ao @ Wo^T
    gemm_tc<true><<<dim3(D_ / 128, BL_ / 128), thr>>>(
        ao, Wo, out, D_, D_, D_, D_, 0, 0);
}

// round 14
// speedup vs baseline: 2.4160x; 1.1543x over previous
#include <cuda_runtime.h>
#include <cuda_bf16.h>
#include <cstdint>

// Problem dims
#define B_    2
#define L_    2048
#define D_    2048
#define H_    16
#define HD_   128
#define RQ_   1536
#define RKV_  512
#define BL_   (B_ * L_)

#define SCALE_ 0.08838834764831845f  // 1/sqrt(128)

// ---------------- packed split-bf16 storage --------------------------------
// "packed" layout: per row of K floats -> K uint32 words, grouped in chunks of
// 16 floats (=16 stored words). Within a chunk, stored word
//   [4*t+0]=hi(pair t), [4*t+1]=lo(pair t), [4*t+2]=hi(pair t+4), [4*t+3]=lo(pair t+4)
// for t=0..3, where pair w = floats (2w, 2w+1). A uint4 load at offset 4*tig
// yields exactly the hi+lo mma fragment words for lane group tig.
__device__ uint32_t g_hidP[BL_ * D_];
__device__ uint32_t g_qdP [BL_ * RQ_];
__device__ uint32_t g_cP  [BL_ * RKV_];
__device__ uint32_t g_aoP [BL_ * D_];
__device__ uint32_t g_WqdP[RQ_ * D_];
__device__ uint32_t g_WquP[D_ * RQ_];
__device__ uint32_t g_WkvP[RKV_ * D_];
__device__ uint32_t g_WoP [D_ * D_];
__device__ uint32_t g_kupT[H_ * HD_ * RKV_];
__device__ uint32_t g_vupT[H_ * HD_ * RKV_];

__device__ float g_v[BL_ * D_];   // fp32 V for pack_v transpose

// attention operand layouts (separate hi/lo arrays, perm8 within 8-groups)
#define QK_WORDS (32 * 2048 * 64)
#define V_WORDS  (32 * 128 * 1024)
__device__ uint32_t g_Qh[QK_WORDS], g_Ql[QK_WORDS];
__device__ uint32_t g_Kh[QK_WORDS], g_Kl[QK_WORDS];
__device__ uint32_t g_Vh[V_WORDS],  g_Vl[V_WORDS];

// ---------------- helpers --------------------------------------------------
__device__ __forceinline__ void split_pack(float x, float y,
                                           uint32_t& hi, uint32_t& lo) {
    __nv_bfloat162 h = __floats2bfloat162_rn(x, y);
    float rx = x - __bfloat162float(h.x);
    float ry = y - __bfloat162float(h.y);
    __nv_bfloat162 l = __floats2bfloat162_rn(rx, ry);
    hi = reinterpret_cast<uint32_t&>(h);
    lo = reinterpret_cast<uint32_t&>(l);
}

__device__ __forceinline__ void mma_bf16(float* c, const uint32_t* a,
                                         const uint32_t* b) {
    asm("mma.sync.aligned.m16n8k16.row.col.f32.bf16.bf16.f32 "
        "{%0,%1,%2,%3}, {%4,%5,%6,%7}, {%8,%9}, {%0,%1,%2,%3};"
        : "+f"(c[0]), "+f"(c[1]), "+f"(c[2]), "+f"(c[3])
        : "r"(a[0]), "r"(a[1]), "r"(a[2]), "r"(a[3]), "r"(b[0]), "r"(b[1]));
}

__device__ __forceinline__ int perm8(int w) {
    return (w & ~7) | (((w & 3) << 1) | ((w >> 2) & 1));
}

__device__ __forceinline__ void cp16(uint32_t saddr, const uint32_t* g) {
    asm volatile("cp.async.ca.shared.global [%0], [%1], 16;\n"
                 :: "r"(saddr), "l"(g));
}
#define CP_COMMIT() asm volatile("cp.async.commit_group;\n" ::: "memory")
#define CP_WAIT2()  asm volatile("cp.async.wait_group 2;\n" ::: "memory")

// ---------------- pack kernels ---------------------------------------------
// row-major fp32 -> packed (position-independent per 16-float chunk)
__global__ __launch_bounds__(256)
void pack_rm(const float* __restrict__ src, uint32_t* __restrict__ dst,
             int nChunks)
{
    int ci = blockIdx.x * 256 + threadIdx.x;
    if (ci >= nChunks) return;
    const long base = (long)ci * 16;
    float f[16];
    *(float4*)&f[0]  = *(const float4*)&src[base + 0];
    *(float4*)&f[4]  = *(const float4*)&src[base + 4];
    *(float4*)&f[8]  = *(const float4*)&src[base + 8];
    *(float4*)&f[12] = *(const float4*)&src[base + 12];
#pragma unroll
    for (int t = 0; t < 4; ++t) {
        uint32_t h0, l0, h1, l1;
        split_pack(f[2 * t], f[2 * t + 1], h0, l0);
        split_pack(f[2 * t + 8], f[2 * t + 9], h1, l1);
        *(uint4*)&dst[base + 4 * t] = make_uint4(h0, l0, h1, l1);
    }
}

// k_up/v_up [H][512][128] -> transposed packed [H][128 rows][512 words]
__global__ __launch_bounds__(256)
void pack_tr(const float* __restrict__ src, uint32_t* __restrict__ dst)
{
    int idx = blockIdx.x * 256 + threadIdx.x;          // 65536 total
    int hh = idx >> 12, r = (idx >> 5) & 127, c = idx & 31;
    const float* s = src + (long)hh * RKV_ * HD_ + (long)c * 16 * HD_ + r;
    float f[16];
#pragma unroll
    for (int j = 0; j < 16; ++j) f[j] = s[j * HD_];
    uint32_t* d = dst + (long)hh * HD_ * RKV_ + (long)r * RKV_ + c * 16;
#pragma unroll
    for (int t = 0; t < 4; ++t) {
        uint32_t h0, l0, h1, l1;
        split_pack(f[2 * t], f[2 * t + 1], h0, l0);
        split_pack(f[2 * t + 8], f[2 * t + 9], h1, l1);
        *(uint4*)&d[4 * t] = make_uint4(h0, l0, h1, l1);
    }
}

// ---------------- packed tensor-core GEMM ----------------------------------
// C[M,N] = A[M,K] * B[N,K]^T, A/B pre-split packed. 128x128 tile, BK=16.
// 3-stage cp.async pipeline; stage = A 2048 + B 2048 words (16KB).
// OUT: 0 = fp32 C, 1 = packed C (next-GEMM A layout), 2 = attention Q/K layout.
template <int OUT>
__global__ __launch_bounds__(256, 2)
void gemm_p(const uint32_t* __restrict__ A, const uint32_t* __restrict__ B,
            float* __restrict__ Cf, uint32_t* __restrict__ P0,
            uint32_t* __restrict__ P1,
            int K, int ldcw, int ldc, long bStride, int cOff, int colZ)
{
    __shared__ uint32_t sh[3 * 4096];

    const int tid  = threadIdx.x;
    const int row0 = blockIdx.y * 128;
    const int col0 = blockIdx.x * 128;
    const uint32_t* Bz = B + (long)blockIdx.z * bStride;

    const int lane = tid & 31, warp = tid >> 5;
    const int wm = warp & 1, wn = warp >> 1;
    const int g = lane >> 2, tig = lane & 3;

    const uint32_t sbase = (uint32_t)__cvta_generic_to_shared(sh);

    float acc[4][4][4];
#pragma unroll
    for (int mi = 0; mi < 4; mi++)
#pragma unroll
        for (int ni = 0; ni < 4; ni++)
#pragma unroll
            for (int r = 0; r < 4; r++) acc[mi][ni][r] = 0.f;

    const int nt = K / 16;

    // loader: 512 uint4 per operand per tile; thread does idx, idx+256
    const int i0 = tid, i1 = tid + 256;
    const int ar0 = row0 + (i0 >> 2), ar1 = row0 + (i1 >> 2);
    const int br0 = col0 + (i0 >> 2), br1 = col0 + (i1 >> 2);
    const int w0 = (i0 & 3) * 4, w1 = (i1 & 3) * 4;

#define GP_ISSUE(st, t)                                                       \
    do {                                                                      \
        const uint32_t sb = sbase + (st) * 4096 * 4;                          \
        cp16(sb + i0 * 16, A + (long)ar0 * K + (t) * 16 + w0);                \
        cp16(sb + i1 * 16, A + (long)ar1 * K + (t) * 16 + w1);                \
        cp16(sb + 8192 + i0 * 16, Bz + (long)br0 * K + (t) * 16 + w0);        \
        cp16(sb + 8192 + i1 * 16, Bz + (long)br1 * K + (t) * 16 + w1);        \
    } while (0)

    GP_ISSUE(0, 0); CP_COMMIT();
    GP_ISSUE(1, 1); CP_COMMIT();
    GP_ISSUE(2, 2); CP_COMMIT();

    for (int t = 0; t < nt; ++t) {
        CP_WAIT2();
        __syncthreads();
        const uint32_t* As_ = sh + (t % 3) * 4096;
        const uint32_t* Bs_ = As_ + 2048;

        uint4 bv[4];
#pragma unroll
        for (int ni = 0; ni < 4; ++ni)
            bv[ni] = *(const uint4*)&Bs_[(wn * 32 + ni * 8 + g) * 16 + 4 * tig];

#pragma unroll
        for (int mi = 0; mi < 4; ++mi) {
            const int ro = (wm * 64 + mi * 16 + g) * 16 + 4 * tig;
            uint4 a0 = *(const uint4*)&As_[ro];
            uint4 a1 = *(const uint4*)&As_[ro + 8 * 16];
            uint32_t ah[4] = {a0.x, a1.x, a0.z, a1.z};
            uint32_t al[4] = {a0.y, a1.y, a0.w, a1.w};
#pragma unroll
            for (int ni = 0; ni < 4; ++ni) {
                uint32_t bh[2] = {bv[ni].x, bv[ni].z};
                uint32_t bl[2] = {bv[ni].y, bv[ni].w};
                mma_bf16(acc[mi][ni], ah, bh);
                mma_bf16(acc[mi][ni], ah, bl);
                mma_bf16(acc[mi][ni], al, bh);
            }
        }
        __syncthreads();
        if (t + 3 < nt) GP_ISSUE((t + 3) % 3, t + 3);
        CP_COMMIT();
    }
#undef GP_ISSUE

    // ---- epilogue ----
#pragma unroll
    for (int mi = 0; mi < 4; ++mi) {
        const int r0 = row0 + wm * 64 + mi * 16 + g;
#pragma unroll
        for (int ni = 0; ni < 4; ++ni) {
            float* ac = acc[mi][ni];
            const int col = col0 + wn * 32 + ni * 8 + tig * 2;
            if (OUT == 0) {
                float* p = Cf + (long)r0 * ldc + blockIdx.z * cOff + col;
                *(float2*)p = make_float2(ac[0], ac[1]);
                *(float2*)(p + 8L * ldc) = make_float2(ac[2], ac[3]);
            } else if (OUT == 1) {
                const int w = col >> 1, ch = w >> 3, tt = w & 7;
                const int pos = ch * 16 + 4 * (tt & 3) + ((tt & 4) ? 2 : 0);
                uint32_t h0, l0, h1, l1;
                split_pack(ac[0], ac[1], h0, l0);
                split_pack(ac[2], ac[3], h1, l1);
                *(uint2*)&P0[(long)r0 * ldcw + pos] = make_uint2(h0, l0);
                *(uint2*)&P0[(long)(r0 + 8) * ldcw + pos] = make_uint2(h1, l1);
            } else {
                const int gc = blockIdx.z * colZ + col;
                const int hh = gc >> 7, w = (gc & 127) >> 1;
                const int bb = r0 >> 11, ll = r0 & 2047;
                const long d0 = ((long)(bb * 16 + hh) << 17) + ll * 64 + perm8(w);
                const long d1 = d0 + 8 * 64;
                uint32_t h0, l0, h1, l1;
                split_pack(ac[0], ac[1], h0, l0);
                split_pack(ac[2], ac[3], h1, l1);
                P0[d0] = h0; P1[d0] = l0;
                P0[d1] = h1; P1[d1] = l1;
            }
        }
    }
}

// ---------------- pack V: transpose + split --------------------------------
__global__ __launch_bounds__(256)
void pack_v(const float* __restrict__ V,
            uint32_t* __restrict__ Vh, uint32_t* __restrict__ Vl)
{
    __shared__ float vs[64][65];
    const int tid = threadIdx.x;
    const int l0 = blockIdx.x * 64, d0 = blockIdx.y * 64;
    const int bh = blockIdx.z, b = bh >> 4, h = bh & 15;
#pragma unroll
    for (int it = 0; it < 4; ++it) {
        int fid = tid + it * 256;
        int l = fid >> 4, part = fid & 15;
        float4 f = *(const float4*)&V[((long)(b * L_ + l0 + l)) * D_
                                      + h * HD_ + d0 + part * 4];
        vs[l][part * 4 + 0] = f.x; vs[l][part * 4 + 1] = f.y;
        vs[l][part * 4 + 2] = f.z; vs[l][part * 4 + 3] = f.w;
    }
    __syncthreads();
#pragma unroll
    for (int it = 0; it < 8; ++it) {
        int wi = tid + it * 256;
        int d = wi >> 5, lw = wi & 31;
        uint32_t hi, lo;
        split_pack(vs[2 * lw][d], vs[2 * lw + 1][d], hi, lo);
        const long dsti = (long)bh * 131072 + (long)(d0 + d) * 1024
                          + (l0 >> 1) + perm8(lw);
        Vh[dsti] = hi; Vl[dsti] = lo;
    }
}

// ---------------- tensor-core flash attention ------------------------------
#define AT_QS_ST 72
#define AT_VS_ST 40
#define AT_SMEM_BYTES (19712 * 4)

__global__ __launch_bounds__(256, 2)
void attn_tc(const uint32_t* __restrict__ Qh, const uint32_t* __restrict__ Ql,
             const uint32_t* __restrict__ Kh, const uint32_t* __restrict__ Kl,
             const uint32_t* __restrict__ Vh, const uint32_t* __restrict__ Vl,
             uint32_t* __restrict__ aoP)
{
    extern __shared__ uint32_t sw[];
    uint32_t* QsH = sw;                 // 64 x 72
    uint32_t* QsL = sw + 4608;
    uint32_t* KsH = sw + 9216;          // 64 x 72
    uint32_t* KsL = sw + 13824;
    uint32_t* VsH = sw + 9216;          // 128 x 40 (shares buffer with Ks)
    uint32_t* VsL = sw + 14336;
    float* redA = (float*)(sw + 19456); // [2][64]
    float* redB = (float*)(sw + 19584); // [2][64]
    float* Ost  = (float*)(sw + 9216);  // 64 x 132 (reuses KV buffer)

    const int tid = threadIdx.x;
    const int lane = tid & 31, warp = tid >> 5;
    const int wm = warp & 3, wn = warp >> 2;
    const int g = lane >> 2, tig = lane & 3;
    const int bh = blockIdx.y;
    const int b = bh >> 4, h = bh & 15;
    const int qt = gridDim.x - 1 - blockIdx.x;   // heavy tiles first
    const int q0 = qt * 64;
    const float slope = exp2f(-0.5f * (float)(h + 1));
    const long qkbase = (long)bh * 131072;
    const long vbase  = (long)bh * 131072;
    const int rowA = wm * 16 + g;

#pragma unroll
    for (int it = 0; it < 8; ++it) {
        int fid = tid + it * 256;
        int arr = fid >> 10, rem = fid & 1023;
        int r = rem >> 4, part = rem & 15;
        const uint32_t* src = (arr ? Ql : Qh) + qkbase + (long)(q0 + r) * 64 + part * 4;
        uint32_t* dst = (arr ? QsL : QsH) + r * AT_QS_ST + part * 4;
        *(uint4*)dst = *(const uint4*)src;
    }
#pragma unroll
    for (int it = 0; it < 8; ++it) {
        int fid = tid + it * 256;
        int arr = fid >> 10, rem = fid & 1023;
        int r = rem >> 4, part = rem & 15;
        const uint32_t* src = (arr ? Kl : Kh) + qkbase + (long)r * 64 + part * 4;
        uint32_t* dst = (arr ? KsL : KsH) + r * AT_QS_ST + part * 4;
        *(uint4*)dst = *(const uint4*)src;
    }
    __syncthreads();

    float m0 = -1e30f, m1 = -1e30f, l0 = 0.f, l1 = 0.f;
    float o[16][4];
#pragma unroll
    for (int ni = 0; ni < 16; ni++)
#pragma unroll
        for (int r = 0; r < 4; r++) o[ni][r] = 0.f;

    for (int kt = 0; kt <= qt; ++kt) {
        const int j0 = kt * 64;

        float s[4][4];
#pragma unroll
        for (int ni = 0; ni < 4; ni++)
#pragma unroll
            for (int r = 0; r < 4; r++) s[ni][r] = 0.f;

#pragma unroll
        for (int kc = 0; kc < 8; ++kc) {
            const int ao_ = rowA * AT_QS_ST + kc * 8 + 2 * tig;
            uint2 qh0 = *(uint2*)&QsH[ao_];
            uint2 qh1 = *(uint2*)&QsH[ao_ + 8 * AT_QS_ST];
            uint2 ql0 = *(uint2*)&QsL[ao_];
            uint2 ql1 = *(uint2*)&QsL[ao_ + 8 * AT_QS_ST];
            uint32_t ah[4] = {qh0.x, qh1.x, qh0.y, qh1.y};
            uint32_t al[4] = {ql0.x, ql1.x, ql0.y, ql1.y};
#pragma unroll
            for (int ni = 0; ni < 4; ++ni) {
                const int bo = (wn * 32 + ni * 8 + g) * AT_QS_ST + kc * 8 + 2 * tig;
                uint2 kh2 = *(uint2*)&KsH[bo];
                uint2 kl2 = *(uint2*)&KsL[bo];
                uint32_t bhp[2] = {kh2.x, kh2.y};
                uint32_t blp[2] = {kl2.x, kl2.y};
                mma_bf16(s[ni], ah, bhp);
                mma_bf16(s[ni], ah, blp);
                mma_bf16(s[ni], al, bhp);
            }
        }

        const bool diag = (kt == qt);
        float mx0 = -1e30f, mx1 = -1e30f;
#pragma unroll
        for (int ni = 0; ni < 4; ++ni) {
#pragma unroll
            for (int r = 0; r < 4; ++r) {
                const int ig = q0 + rowA + ((r >= 2) ? 8 : 0);
                const int jg = j0 + wn * 32 + ni * 8 + 2 * tig + (r & 1);
                float val = s[ni][r] * SCALE_ - slope * (float)(ig - jg);
                if (diag && jg > ig) val = -1e30f;
                s[ni][r] = val;
                if (r < 2) mx0 = fmaxf(mx0, val); else mx1 = fmaxf(mx1, val);
            }
        }
        mx0 = fmaxf(mx0, __shfl_xor_sync(0xffffffffu, mx0, 1));
        mx0 = fmaxf(mx0, __shfl_xor_sync(0xffffffffu, mx0, 2));
        mx1 = fmaxf(mx1, __shfl_xor_sync(0xffffffffu, mx1, 1));
        mx1 = fmaxf(mx1, __shfl_xor_sync(0xffffffffu, mx1, 2));
        if (tig == 0) {
            redA[wn * 64 + rowA] = mx0;
            redA[wn * 64 + rowA + 8] = mx1;
        }
        __syncthreads();

#pragma unroll
        for (int it = 0; it < 8; ++it) {
            int fid = tid + it * 256;
            int arr = fid >> 10, rem = fid & 1023;
            int d = rem >> 3, part = rem & 7;
            const uint32_t* src = (arr ? Vl : Vh) + vbase + (long)d * 1024
                                  + (j0 >> 1) + part * 4;
            uint32_t* dst = (arr ? VsL : VsH) + d * AT_VS_ST + part * 4;
            *(uint4*)dst = *(const uint4*)src;
        }

        const float mn0 = fmaxf(m0, fmaxf(redA[rowA], redA[64 + rowA]));
        const float mn1 = fmaxf(m1, fmaxf(redA[rowA + 8], redA[64 + rowA + 8]));
        float ps0 = 0.f, ps1 = 0.f;
#pragma unroll
        for (int ni = 0; ni < 4; ++ni) {
#pragma unroll
            for (int r = 0; r < 4; ++r) {
                float p = __expf(s[ni][r] - ((r < 2) ? mn0 : mn1));
                s[ni][r] = p;
                if (r < 2) ps0 += p; else ps1 += p;
            }
        }
        ps0 += __shfl_xor_sync(0xffffffffu, ps0, 1);
        ps0 += __shfl_xor_sync(0xffffffffu, ps0, 2);
        ps1 += __shfl_xor_sync(0xffffffffu, ps1, 1);
        ps1 += __shfl_xor_sync(0xffffffffu, ps1, 2);
        if (tig == 0) {
            redB[wn * 64 + rowA] = ps0;
            redB[wn * 64 + rowA + 8] = ps1;
        }
        __syncthreads();

        const float alpha0 = __expf(m0 - mn0);
        const float alpha1 = __expf(m1 - mn1);
        l0 = l0 * alpha0 + redB[rowA] + redB[64 + rowA];
        l1 = l1 * alpha1 + redB[rowA + 8] + redB[64 + rowA + 8];
        m0 = mn0; m1 = mn1;
#pragma unroll
        for (int ni = 0; ni < 16; ++ni) {
            o[ni][0] *= alpha0; o[ni][1] *= alpha0;
            o[ni][2] *= alpha1; o[ni][3] *= alpha1;
        }

        uint32_t ph[4][2], pl[4][2];
#pragma unroll
        for (int ni = 0; ni < 4; ++ni) {
            split_pack(s[ni][0], s[ni][1], ph[ni][0], pl[ni][0]);
            split_pack(s[ni][2], s[ni][3], ph[ni][1], pl[ni][1]);
        }
#pragma unroll
        for (int jcl = 0; jcl < 2; ++jcl) {
            uint32_t pah[4] = {ph[2 * jcl][0], ph[2 * jcl][1],
                               ph[2 * jcl + 1][0], ph[2 * jcl + 1][1]};
            uint32_t pal[4] = {pl[2 * jcl][0], pl[2 * jcl][1],
                               pl[2 * jcl + 1][0], pl[2 * jcl + 1][1]};
#pragma unroll
            for (int ni = 0; ni < 16; ++ni) {
                const int vo = (ni * 8 + g) * AT_VS_ST + wn * 16 + jcl * 8 + 2 * tig;
                uint2 vh2 = *(uint2*)&VsH[vo];
                uint2 vl2 = *(uint2*)&VsL[vo];
                uint32_t vbh[2] = {vh2.x, vh2.y};
                uint32_t vbl[2] = {vl2.x, vl2.y};
                mma_bf16(o[ni], pah, vbh);
                mma_bf16(o[ni], pah, vbl);
                mma_bf16(o[ni], pal, vbh);
            }
        }
        __syncthreads();

        if (kt < qt) {
            const int jn = (kt + 1) * 64;
#pragma unroll
            for (int it = 0; it < 8; ++it) {
                int fid = tid + it * 256;
                int arr = fid >> 10, rem = fid & 1023;
                int r = rem >> 4, part = rem & 15;
                const uint32_t* src = (arr ? Kl : Kh) + qkbase
                                      + (long)(jn + r) * 64 + part * 4;
                uint32_t* dst = (arr ? KsL : KsH) + r * AT_QS_ST + part * 4;
                *(uint4*)dst = *(const uint4*)src;
            }
            __syncthreads();
        }
    }

    // ---- combine wn halves, normalize, store packed ao ----
    __syncthreads();
    if (wn == 1) {
#pragma unroll
        for (int ni = 0; ni < 16; ++ni) {
            const int col = ni * 8 + 2 * tig;
            *(float2*)&Ost[rowA * 132 + col] = make_float2(o[ni][0], o[ni][1]);
            *(float2*)&Ost[(rowA + 8) * 132 + col] = make_float2(o[ni][2], o[ni][3]);
        }
    }
    __syncthreads();
    if (wn == 0) {
        const float inv0 = 1.f / l0, inv1 = 1.f / l1;
        const long r0w = (long)(b * L_ + q0 + rowA) * 2048;
        const long r1w = r0w + 8L * 2048;
#pragma unroll
        for (int ni = 0; ni < 16; ++ni) {
            const int col = ni * 8 + 2 * tig;
            float2 a0 = *(float2*)&Ost[rowA * 132 + col];
            float2 a1 = *(float2*)&Ost[(rowA + 8) * 132 + col];
            const float v0 = (o[ni][0] + a0.x) * inv0;
            const float v1 = (o[ni][1] + a0.y) * inv0;
            const float v2 = (o[ni][2] + a1.x) * inv1;
            const float v3 = (o[ni][3] + a1.y) * inv1;
            const int w = h * 64 + ni * 4 + tig;
            const int ch = w >> 3, tt = w & 7;
            const int pos = ch * 16 + 4 * (tt & 3) + ((tt & 4) ? 2 : 0);
            uint32_t hw, lw;
            split_pack(v0, v1, hw, lw);
            *(uint2*)&aoP[r0w + pos] = make_uint2(hw, lw);
            split_pack(v2, v3, hw, lw);
            *(uint2*)&aoP[r1w + pos] = make_uint2(hw, lw);
        }
    }
}

// ---------------- launch ---------------------------------------------------
extern "C" void kernel_launch(void* const* d_in, const int* in_sizes, int n_in,
                              void* d_out, int out_size)
{
    const float* hidden   = (const float*)d_in[0];
    const float* Wq_down  = (const float*)d_in[1];
    const float* Wq_up    = (const float*)d_in[2];
    const float* Wkv_down = (const float*)d_in[3];
    const float* k_up     = (const float*)d_in[4];
    const float* v_up     = (const float*)d_in[5];
    const float* Wo       = (const float*)d_in[6];
    float* out = (float*)d_out;

    void* p;
    cudaGetSymbolAddress(&p, g_hidP); uint32_t* hidP = (uint32_t*)p;
    cudaGetSymbolAddress(&p, g_qdP);  uint32_t* qdP  = (uint32_t*)p;
    cudaGetSymbolAddress(&p, g_cP);   uint32_t* cP   = (uint32_t*)p;
    cudaGetSymbolAddress(&p, g_aoP);  uint32_t* aoP  = (uint32_t*)p;
    cudaGetSymbolAddress(&p, g_WqdP); uint32_t* WqdP = (uint32_t*)p;
    cudaGetSymbolAddress(&p, g_WquP); uint32_t* WquP = (uint32_t*)p;
    cudaGetSymbolAddress(&p, g_WkvP); uint32_t* WkvP = (uint32_t*)p;
    cudaGetSymbolAddress(&p, g_WoP);  uint32_t* WoP  = (uint32_t*)p;
    cudaGetSymbolAddress(&p, g_kupT); uint32_t* kupT = (uint32_t*)p;
    cudaGetSymbolAddress(&p, g_vupT); uint32_t* vupT = (uint32_t*)p;
    cudaGetSymbolAddress(&p, g_v);    float* v = (float*)p;
    cudaGetSymbolAddress(&p, g_Qh); uint32_t* Qh = (uint32_t*)p;
    cudaGetSymbolAddress(&p, g_Ql); uint32_t* Ql = (uint32_t*)p;
    cudaGetSymbolAddress(&p, g_Kh); uint32_t* Kh = (uint32_t*)p;
    cudaGetSymbolAddress(&p, g_Kl); uint32_t* Kl = (uint32_t*)p;
    cudaGetSymbolAddress(&p, g_Vh); uint32_t* Vh = (uint32_t*)p;
    cudaGetSymbolAddress(&p, g_Vl); uint32_t* Vl = (uint32_t*)p;

    cudaFuncSetAttribute(attn_tc,
                         cudaFuncAttributeMaxDynamicSharedMemorySize,
                         AT_SMEM_BYTES);

    const dim3 thr(256);

    // 0. pack inputs
    pack_rm<<<(BL_ * D_ / 16 + 255) / 256, thr>>>(hidden, hidP, BL_ * D_ / 16);
    pack_rm<<<(RQ_ * D_ / 16 + 255) / 256, thr>>>(Wq_down, WqdP, RQ_ * D_ / 16);
    pack_rm<<<(D_ * RQ_ / 16 + 255) / 256, thr>>>(Wq_up, WquP, D_ * RQ_ / 16);
    pack_rm<<<(RKV_ * D_ / 16 + 255) / 256, thr>>>(Wkv_down, WkvP, RKV_ * D_ / 16);
    pack_rm<<<(D_ * D_ / 16 + 255) / 256, thr>>>(Wo, WoP, D_ * D_ / 16);
    pack_tr<<<256, thr>>>(k_up, kupT);
    pack_tr<<<256, thr>>>(v_up, vupT);

    // 1. qdown = hidden @ Wq_down^T  -> packed
    gemm_p<1><<<dim3(RQ_ / 128, BL_ / 128), thr>>>(
        hidP, WqdP, nullptr, qdP, nullptr, D_, RQ_, 0, 0, 0, 0);
    // 2. q = qdown @ Wq_up^T -> attention Q layout
    gemm_p<2><<<dim3(D_ / 128, BL_ / 128), thr>>>(
        qdP, WquP, nullptr, Qh, Ql, RQ_, 0, 0, 0, 0, 0);
    // 3. c = hidden @ Wkv_down^T -> packed
    gemm_p<1><<<dim3(RKV_ / 128, BL_ / 128), thr>>>(
        hidP, WkvP, nullptr, cP, nullptr, D_, RKV_, 0, 0, 0, 0);
    // 4. k per head -> attention K layout
    gemm_p<2><<<dim3(1, BL_ / 128, H_), thr>>>(
        cP, kupT, nullptr, Kh, Kl, RKV_, 0, 0, (long)HD_ * RKV_, 0, HD_);
    // 5. v per head -> fp32
    gemm_p<0><<<dim3(1, BL_ / 128, H_), thr>>>(
        cP, vupT, v, nullptr, nullptr, RKV_, 0, D_, (long)HD_ * RKV_, HD_, 0);
    // 6. pack V (transpose + split)
    pack_v<<<dim3(L_ / 64, HD_ / 64, B_ * H_), thr>>>(v, Vh, Vl);
    // 7. attention -> packed ao
    attn_tc<<<dim3(L_ / 64, B_ * H_), thr, AT_SMEM_BYTES>>>(
        Qh, Ql, Kh, Kl, Vh, Vl, aoP);
    // 8. out = ao @ Wo^T -> fp32
    gemm_p<0><<<dim3(D_ / 128, BL_ / 128), thr>>>(
        aoP, WoP, out, nullptr, nullptr, D_, 0, D_, 0, 0, 0);
}

// round 15
// speedup vs baseline: 2.4555x; 1.0164x over previous
#include <cuda_runtime.h>
#include <cuda_bf16.h>
#include <cstdint>

// Problem dims
#define B_    2
#define L_    2048
#define D_    2048
#define H_    16
#define HD_   128
#define RQ_   1536
#define RKV_  512
#define BL_   (B_ * L_)

#define SCALE_ 0.08838834764831845f  // 1/sqrt(128)

// ---------------- packed split-bf16 storage --------------------------------
__device__ uint32_t g_hidP[BL_ * D_];
__device__ uint32_t g_qdP [BL_ * RQ_];
__device__ uint32_t g_cP  [BL_ * RKV_];
__device__ uint32_t g_aoP [BL_ * D_];
__device__ uint32_t g_WqdP[RQ_ * D_];
__device__ uint32_t g_WquP[D_ * RQ_];
__device__ uint32_t g_WkvP[RKV_ * D_];
__device__ uint32_t g_WoP [D_ * D_];
__device__ uint32_t g_kupT[H_ * HD_ * RKV_];
__device__ uint32_t g_vupT[H_ * HD_ * RKV_];

__device__ float g_v[BL_ * D_];   // fp32 V for pack_v transpose

#define QK_WORDS (32 * 2048 * 64)
#define V_WORDS  (32 * 128 * 1024)
__device__ uint32_t g_Qh[QK_WORDS], g_Ql[QK_WORDS];
__device__ uint32_t g_Kh[QK_WORDS], g_Kl[QK_WORDS];
__device__ uint32_t g_Vh[V_WORDS],  g_Vl[V_WORDS];

// ---------------- helpers --------------------------------------------------
__device__ __forceinline__ void split_pack(float x, float y,
                                           uint32_t& hi, uint32_t& lo) {
    __nv_bfloat162 h = __floats2bfloat162_rn(x, y);
    float rx = x - __bfloat162float(h.x);
    float ry = y - __bfloat162float(h.y);
    __nv_bfloat162 l = __floats2bfloat162_rn(rx, ry);
    hi = reinterpret_cast<uint32_t&>(h);
    lo = reinterpret_cast<uint32_t&>(l);
}

__device__ __forceinline__ void mma_bf16(float* c, const uint32_t* a,
                                         const uint32_t* b) {
    asm("mma.sync.aligned.m16n8k16.row.col.f32.bf16.bf16.f32 "
        "{%0,%1,%2,%3}, {%4,%5,%6,%7}, {%8,%9}, {%0,%1,%2,%3};"
        : "+f"(c[0]), "+f"(c[1]), "+f"(c[2]), "+f"(c[3])
        : "r"(a[0]), "r"(a[1]), "r"(a[2]), "r"(a[3]), "r"(b[0]), "r"(b[1]));
}

__device__ __forceinline__ int perm8(int w) {
    return (w & ~7) | (((w & 3) << 1) | ((w >> 2) & 1));
}

__device__ __forceinline__ void cp16(uint32_t saddr, const uint32_t* g) {
    asm volatile("cp.async.ca.shared.global [%0], [%1], 16;\n"
                 :: "r"(saddr), "l"(g));
}
#define CP_COMMIT() asm volatile("cp.async.commit_group;\n" ::: "memory")
#define CP_WAIT2()  asm volatile("cp.async.wait_group 2;\n" ::: "memory")
#define CP_WAIT0()  asm volatile("cp.async.wait_group 0;\n" ::: "memory")

// ---------------- pack kernels ---------------------------------------------
__global__ __launch_bounds__(256)
void pack_rm(const float* __restrict__ src, uint32_t* __restrict__ dst,
             int nChunks)
{
    int ci = blockIdx.x * 256 + threadIdx.x;
    if (ci >= nChunks) return;
    const long base = (long)ci * 16;
    float f[16];
    *(float4*)&f[0]  = *(const float4*)&src[base + 0];
    *(float4*)&f[4]  = *(const float4*)&src[base + 4];
    *(float4*)&f[8]  = *(const float4*)&src[base + 8];
    *(float4*)&f[12] = *(const float4*)&src[base + 12];
#pragma unroll
    for (int t = 0; t < 4; ++t) {
        uint32_t h0, l0, h1, l1;
        split_pack(f[2 * t], f[2 * t + 1], h0, l0);
        split_pack(f[2 * t + 8], f[2 * t + 9], h1, l1);
        *(uint4*)&dst[base + 4 * t] = make_uint4(h0, l0, h1, l1);
    }
}

__global__ __launch_bounds__(256)
void pack_tr(const float* __restrict__ src, uint32_t* __restrict__ dst)
{
    int idx = blockIdx.x * 256 + threadIdx.x;
    int hh = idx >> 12, r = (idx >> 5) & 127, c = idx & 31;
    const float* s = src + (long)hh * RKV_ * HD_ + (long)c * 16 * HD_ + r;
    float f[16];
#pragma unroll
    for (int j = 0; j < 16; ++j) f[j] = s[j * HD_];
    uint32_t* d = dst + (long)hh * HD_ * RKV_ + (long)r * RKV_ + c * 16;
#pragma unroll
    for (int t = 0; t < 4; ++t) {
        uint32_t h0, l0, h1, l1;
        split_pack(f[2 * t], f[2 * t + 1], h0, l0);
        split_pack(f[2 * t + 8], f[2 * t + 9], h1, l1);
        *(uint4*)&d[4 * t] = make_uint4(h0, l0, h1, l1);
    }
}

// ---------------- packed tensor-core GEMM ----------------------------------
template <int OUT>
__global__ __launch_bounds__(256, 2)
void gemm_p(const uint32_t* __restrict__ A, const uint32_t* __restrict__ B,
            float* __restrict__ Cf, uint32_t* __restrict__ P0,
            uint32_t* __restrict__ P1,
            int K, int ldcw, int ldc, long bStride, int cOff, int colZ)
{
    __shared__ uint32_t sh[3 * 4096];

    const int tid  = threadIdx.x;
    const int row0 = blockIdx.y * 128;
    const int col0 = blockIdx.x * 128;
    const uint32_t* Bz = B + (long)blockIdx.z * bStride;

    const int lane = tid & 31, warp = tid >> 5;
    const int wm = warp & 1, wn = warp >> 1;
    const int g = lane >> 2, tig = lane & 3;

    const uint32_t sbase = (uint32_t)__cvta_generic_to_shared(sh);

    float acc[4][4][4];
#pragma unroll
    for (int mi = 0; mi < 4; mi++)
#pragma unroll
        for (int ni = 0; ni < 4; ni++)
#pragma unroll
            for (int r = 0; r < 4; r++) acc[mi][ni][r] = 0.f;

    const int nt = K / 16;

    const int i0 = tid, i1 = tid + 256;
    const int ar0 = row0 + (i0 >> 2), ar1 = row0 + (i1 >> 2);
    const int br0 = col0 + (i0 >> 2), br1 = col0 + (i1 >> 2);
    const int w0 = (i0 & 3) * 4, w1 = (i1 & 3) * 4;

#define GP_ISSUE(st, t)                                                       \
    do {                                                                      \
        const uint32_t sb = sbase + (st) * 4096 * 4;                          \
        cp16(sb + i0 * 16, A + (long)ar0 * K + (t) * 16 + w0);                \
        cp16(sb + i1 * 16, A + (long)ar1 * K + (t) * 16 + w1);                \
        cp16(sb + 8192 + i0 * 16, Bz + (long)br0 * K + (t) * 16 + w0);        \
        cp16(sb + 8192 + i1 * 16, Bz + (long)br1 * K + (t) * 16 + w1);        \
    } while (0)

    GP_ISSUE(0, 0); CP_COMMIT();
    GP_ISSUE(1, 1); CP_COMMIT();
    GP_ISSUE(2, 2); CP_COMMIT();

    for (int t = 0; t < nt; ++t) {
        CP_WAIT2();
        __syncthreads();
        const uint32_t* As_ = sh + (t % 3) * 4096;
        const uint32_t* Bs_ = As_ + 2048;

        uint4 bv[4];
#pragma unroll
        for (int ni = 0; ni < 4; ++ni)
            bv[ni] = *(const uint4*)&Bs_[(wn * 32 + ni * 8 + g) * 16 + 4 * tig];

#pragma unroll
        for (int mi = 0; mi < 4; ++mi) {
            const int ro = (wm * 64 + mi * 16 + g) * 16 + 4 * tig;
            uint4 a0 = *(const uint4*)&As_[ro];
            uint4 a1 = *(const uint4*)&As_[ro + 8 * 16];
            uint32_t ah[4] = {a0.x, a1.x, a0.z, a1.z};
            uint32_t al[4] = {a0.y, a1.y, a0.w, a1.w};
#pragma unroll
            for (int ni = 0; ni < 4; ++ni) {
                uint32_t bh[2] = {bv[ni].x, bv[ni].z};
                uint32_t bl[2] = {bv[ni].y, bv[ni].w};
                mma_bf16(acc[mi][ni], ah, bh);
                mma_bf16(acc[mi][ni], ah, bl);
                mma_bf16(acc[mi][ni], al, bh);
            }
        }
        __syncthreads();
        if (t + 3 < nt) GP_ISSUE((t + 3) % 3, t + 3);
        CP_COMMIT();
    }
#undef GP_ISSUE

#pragma unroll
    for (int mi = 0; mi < 4; ++mi) {
        const int r0 = row0 + wm * 64 + mi * 16 + g;
#pragma unroll
        for (int ni = 0; ni < 4; ++ni) {
            float* ac = acc[mi][ni];
            const int col = col0 + wn * 32 + ni * 8 + tig * 2;
            if (OUT == 0) {
                float* p = Cf + (long)r0 * ldc + blockIdx.z * cOff + col;
                *(float2*)p = make_float2(ac[0], ac[1]);
                *(float2*)(p + 8L * ldc) = make_float2(ac[2], ac[3]);
            } else if (OUT == 1) {
                const int w = col >> 1, ch = w >> 3, tt = w & 7;
                const int pos = ch * 16 + 4 * (tt & 3) + ((tt & 4) ? 2 : 0);
                uint32_t h0, l0, h1, l1;
                split_pack(ac[0], ac[1], h0, l0);
                split_pack(ac[2], ac[3], h1, l1);
                *(uint2*)&P0[(long)r0 * ldcw + pos] = make_uint2(h0, l0);
                *(uint2*)&P0[(long)(r0 + 8) * ldcw + pos] = make_uint2(h1, l1);
            } else {
                const int gc = blockIdx.z * colZ + col;
                const int hh = gc >> 7, w = (gc & 127) >> 1;
                const int bb = r0 >> 11, ll = r0 & 2047;
                const long d0 = ((long)(bb * 16 + hh) << 17) + ll * 64 + perm8(w);
                const long d1 = d0 + 8 * 64;
                uint32_t h0, l0, h1, l1;
                split_pack(ac[0], ac[1], h0, l0);
                split_pack(ac[2], ac[3], h1, l1);
                P0[d0] = h0; P1[d0] = l0;
                P0[d1] = h1; P1[d1] = l1;
            }
        }
    }
}

// ---------------- pack V: transpose + split --------------------------------
__global__ __launch_bounds__(256)
void pack_v(const float* __restrict__ V,
            uint32_t* __restrict__ Vh, uint32_t* __restrict__ Vl)
{
    __shared__ float vs[64][65];
    const int tid = threadIdx.x;
    const int l0 = blockIdx.x * 64, d0 = blockIdx.y * 64;
    const int bh = blockIdx.z, b = bh >> 4, h = bh & 15;
#pragma unroll
    for (int it = 0; it < 4; ++it) {
        int fid = tid + it * 256;
        int l = fid >> 4, part = fid & 15;
        float4 f = *(const float4*)&V[((long)(b * L_ + l0 + l)) * D_
                                      + h * HD_ + d0 + part * 4];
        vs[l][part * 4 + 0] = f.x; vs[l][part * 4 + 1] = f.y;
        vs[l][part * 4 + 2] = f.z; vs[l][part * 4 + 3] = f.w;
    }
    __syncthreads();
#pragma unroll
    for (int it = 0; it < 8; ++it) {
        int wi = tid + it * 256;
        int d = wi >> 5, lw = wi & 31;
        uint32_t hi, lo;
        split_pack(vs[2 * lw][d], vs[2 * lw + 1][d], hi, lo);
        const long dsti = (long)bh * 131072 + (long)(d0 + d) * 1024
                          + (l0 >> 1) + perm8(lw);
        Vh[dsti] = hi; Vl[dsti] = lo;
    }
}

// ---------------- tensor-core flash attention v2 ---------------------------
// BQ=128, BK=64. 8 warps; warp w owns rows w*16..w*16+15 x ALL 64 cols ->
// softmax is warp-local (no smem reductions, no O combine). cp.async
// double-buffered K and V; ONE __syncthreads per K-tile.
// smem words: QsH/QsL 2x(128x72)=18432 | KsH/KsL 2 stages 2x(2x64x72)=18432
//             VsH/VsL 2 stages 2x(2x128x32)=16384  -> 53248 words = 212992 B
#define AQ_ST 72
#define AT2_SMEM_BYTES (53248 * 4)

__global__ __launch_bounds__(256, 1)
void attn_tc2(const uint32_t* __restrict__ Qh, const uint32_t* __restrict__ Ql,
              const uint32_t* __restrict__ Kh, const uint32_t* __restrict__ Kl,
              const uint32_t* __restrict__ Vh, const uint32_t* __restrict__ Vl,
              uint32_t* __restrict__ aoP)
{
    extern __shared__ uint32_t sw2[];
    uint32_t* QsH = sw2;              // 128 x 72
    uint32_t* QsL = sw2 + 9216;
    uint32_t* KsH = sw2 + 18432;      // 2 stages x 64 x 72
    uint32_t* KsL = sw2 + 27648;
    uint32_t* VsH = sw2 + 36864;      // 2 stages x 128 x 32 (xor-8 swizzle)
    uint32_t* VsL = sw2 + 45056;
    const uint32_t sbase = (uint32_t)__cvta_generic_to_shared(sw2);

    const int tid = threadIdx.x;
    const int lane = tid & 31, warp = tid >> 5;
    const int g = lane >> 2, tig = lane & 3;
    const int bh = blockIdx.y;
    const int b = bh >> 4, h = bh & 15;
    const int qt = gridDim.x - 1 - blockIdx.x;   // heavy tiles first
    const int q0 = qt * 128;
    const float slope = exp2f(-0.5f * (float)(h + 1));
    const long qkbase = (long)bh * 131072;
    const long vbase  = (long)bh * 131072;
    const int rowA = warp * 16 + g;

    // ---- prologue: Q (whole tile) + K0 + V0 via cp.async, one group ----
#pragma unroll
    for (int it = 0; it < 16; ++it) {            // Q: 4096 chunks
        int fid = tid + it * 256;
        int arr = fid >> 11, rem = fid & 2047;
        int r = rem >> 4, part = rem & 15;
        cp16(sbase + ((arr ? 9216 : 0) + r * AQ_ST + part * 4) * 4,
             (arr ? Ql : Qh) + qkbase + (long)(q0 + r) * 64 + part * 4);
    }
#pragma unroll
    for (int it = 0; it < 8; ++it) {             // K0: 2048 chunks
        int fid = tid + it * 256;
        int arr = fid >> 10, rem = fid & 1023;
        int r = rem >> 4, part = rem & 15;
        cp16(sbase + ((18432 + arr * 9216) + r * AQ_ST + part * 4) * 4,
             (arr ? Kl : Kh) + qkbase + (long)r * 64 + part * 4);
    }
#pragma unroll
    for (int it = 0; it < 8; ++it) {             // V0: 2048 chunks
        int fid = tid + it * 256;
        int arr = fid >> 10, rem = fid & 1023;
        int d = rem >> 3, part = rem & 7;
        cp16(sbase + ((36864 + arr * 8192) + d * 32
                      + ((part * 4) ^ ((d & 3) << 3))) * 4,
             (arr ? Vl : Vh) + vbase + (long)d * 1024 + part * 4);
    }
    CP_COMMIT();

    float m0 = -1e30f, m1 = -1e30f, l0 = 0.f, l1 = 0.f;
    float o[16][4];
#pragma unroll
    for (int ni = 0; ni < 16; ni++)
#pragma unroll
        for (int r = 0; r < 4; r++) o[ni][r] = 0.f;

    const int ktmax = 2 * qt + 1;
    for (int kt = 0; kt <= ktmax; ++kt) {
        const int cur = kt & 1;
        const int j0 = kt * 64;

        CP_WAIT0();
        __syncthreads();

        // ---- prefetch next K/V into other stage (overlaps compute) ----
        if (kt < ktmax) {
            const int nst = cur ^ 1;
            const int jn = (kt + 1) * 64;
#pragma unroll
            for (int it = 0; it < 8; ++it) {
                int fid = tid + it * 256;
                int arr = fid >> 10, rem = fid & 1023;
                int r = rem >> 4, part = rem & 15;
                cp16(sbase + ((18432 + arr * 9216 + nst * 4608)
                              + r * AQ_ST + part * 4) * 4,
                     (arr ? Kl : Kh) + qkbase + (long)(jn + r) * 64 + part * 4);
            }
#pragma unroll
            for (int it = 0; it < 8; ++it) {
                int fid = tid + it * 256;
                int arr = fid >> 10, rem = fid & 1023;
                int d = rem >> 3, part = rem & 7;
                cp16(sbase + ((36864 + arr * 8192 + nst * 4096) + d * 32
                              + ((part * 4) ^ ((d & 3) << 3))) * 4,
                     (arr ? Vl : Vh) + vbase + (long)d * 1024 + (jn >> 1) + part * 4);
            }
            CP_COMMIT();
        }

        const uint32_t* KH = KsH + cur * 4608;
        const uint32_t* KL = KsL + cur * 4608;
        const uint32_t* VH = VsH + cur * 4096;
        const uint32_t* VL = VsL + cur * 4096;

        // ---- S = Q K^T (3-term split), full 64 cols per warp ----
        float s[8][4];
#pragma unroll
        for (int ni = 0; ni < 8; ni++)
#pragma unroll
            for (int r = 0; r < 4; r++) s[ni][r] = 0.f;

#pragma unroll
        for (int kc = 0; kc < 8; ++kc) {
            const int ao_ = rowA * AQ_ST + kc * 8 + 2 * tig;
            uint2 qh0 = *(uint2*)&QsH[ao_];
            uint2 qh1 = *(uint2*)&QsH[ao_ + 8 * AQ_ST];
            uint2 ql0 = *(uint2*)&QsL[ao_];
            uint2 ql1 = *(uint2*)&QsL[ao_ + 8 * AQ_ST];
            uint32_t ah[4] = {qh0.x, qh1.x, qh0.y, qh1.y};
            uint32_t al[4] = {ql0.x, ql1.x, ql0.y, ql1.y};
#pragma unroll
            for (int ni = 0; ni < 8; ++ni) {
                const int bo = (ni * 8 + g) * AQ_ST + kc * 8 + 2 * tig;
                uint2 kh2 = *(uint2*)&KH[bo];
                uint2 kl2 = *(uint2*)&KL[bo];
                uint32_t bhp[2] = {kh2.x, kh2.y};
                uint32_t blp[2] = {kl2.x, kl2.y};
                mma_bf16(s[ni], ah, bhp);
                mma_bf16(s[ni], ah, blp);
                mma_bf16(s[ni], al, bhp);
            }
        }

        // ---- scale + alibi + mask; warp-local row max ----
        const bool msk = (kt >= 2 * qt);
        float mx0 = -1e30f, mx1 = -1e30f;
#pragma unroll
        for (int ni = 0; ni < 8; ++ni) {
#pragma unroll
            for (int r = 0; r < 4; ++r) {
                const int ig = q0 + rowA + ((r >= 2) ? 8 : 0);
                const int jg = j0 + ni * 8 + 2 * tig + (r & 1);
                float val = s[ni][r] * SCALE_ - slope * (float)(ig - jg);
                if (msk && jg > ig) val = -1e30f;
                s[ni][r] = val;
                if (r < 2) mx0 = fmaxf(mx0, val); else mx1 = fmaxf(mx1, val);
            }
        }
        mx0 = fmaxf(mx0, __shfl_xor_sync(0xffffffffu, mx0, 1));
        mx0 = fmaxf(mx0, __shfl_xor_sync(0xffffffffu, mx0, 2));
        mx1 = fmaxf(mx1, __shfl_xor_sync(0xffffffffu, mx1, 1));
        mx1 = fmaxf(mx1, __shfl_xor_sync(0xffffffffu, mx1, 2));

        const float mn0 = fmaxf(m0, mx0);
        const float mn1 = fmaxf(m1, mx1);
        float ps0 = 0.f, ps1 = 0.f;
#pragma unroll
        for (int ni = 0; ni < 8; ++ni) {
#pragma unroll
            for (int r = 0; r < 4; ++r) {
                float p = __expf(s[ni][r] - ((r < 2) ? mn0 : mn1));
                s[ni][r] = p;
                if (r < 2) ps0 += p; else ps1 += p;
            }
        }
        ps0 += __shfl_xor_sync(0xffffffffu, ps0, 1);
        ps0 += __shfl_xor_sync(0xffffffffu, ps0, 2);
        ps1 += __shfl_xor_sync(0xffffffffu, ps1, 1);
        ps1 += __shfl_xor_sync(0xffffffffu, ps1, 2);

        const float alpha0 = __expf(m0 - mn0);
        const float alpha1 = __expf(m1 - mn1);
        l0 = l0 * alpha0 + ps0;
        l1 = l1 * alpha1 + ps1;
        m0 = mn0; m1 = mn1;
#pragma unroll
        for (int ni = 0; ni < 16; ++ni) {
            o[ni][0] *= alpha0; o[ni][1] *= alpha0;
            o[ni][2] *= alpha1; o[ni][3] *= alpha1;
        }

        // ---- pack P frags, PV mma over full d=128 per warp ----
        uint32_t ph[8][2], pl[8][2];
#pragma unroll
        for (int ni = 0; ni < 8; ++ni) {
            split_pack(s[ni][0], s[ni][1], ph[ni][0], pl[ni][0]);
            split_pack(s[ni][2], s[ni][3], ph[ni][1], pl[ni][1]);
        }
#pragma unroll
        for (int jc = 0; jc < 4; ++jc) {
            uint32_t pah[4] = {ph[2 * jc][0], ph[2 * jc][1],
                               ph[2 * jc + 1][0], ph[2 * jc + 1][1]};
            uint32_t pal[4] = {pl[2 * jc][0], pl[2 * jc][1],
                               pl[2 * jc + 1][0], pl[2 * jc + 1][1]};
#pragma unroll
            for (int ni = 0; ni < 16; ++ni) {
                const int vo = (ni * 8 + g) * 32
                               + ((jc * 8 + 2 * tig) ^ ((g & 3) << 3));
                uint2 vh2 = *(uint2*)&VH[vo];
                uint2 vl2 = *(uint2*)&VL[vo];
                uint32_t vbh[2] = {vh2.x, vh2.y};
                uint32_t vbl[2] = {vl2.x, vl2.y};
                mma_bf16(o[ni], pah, vbh);
                mma_bf16(o[ni], pah, vbl);
                mma_bf16(o[ni], pal, vbh);
            }
        }
    }

    // ---- normalize + store packed ao (no cross-warp combine) ----
    const float inv0 = 1.f / l0, inv1 = 1.f / l1;
    const long r0w = (long)(b * L_ + q0 + rowA) * 2048;
    const long r1w = r0w + 8L * 2048;
#pragma unroll
    for (int ni = 0; ni < 16; ++ni) {
        const int w = h * 64 + ni * 4 + tig;
        const int ch = w >> 3, tt = w & 7;
        const int pos = ch * 16 + 4 * (tt & 3) + ((tt & 4) ? 2 : 0);
        uint32_t hw, lw;
        split_pack(o[ni][0] * inv0, o[ni][1] * inv0, hw, lw);
        *(uint2*)&aoP[r0w + pos] = make_uint2(hw, lw);
        split_pack(o[ni][2] * inv1, o[ni][3] * inv1, hw, lw);
        *(uint2*)&aoP[r1w + pos] = make_uint2(hw, lw);
    }
}

// ---------------- launch ---------------------------------------------------
extern "C" void kernel_launch(void* const* d_in, const int* in_sizes, int n_in,
                              void* d_out, int out_size)
{
    const float* hidden   = (const float*)d_in[0];
    const float* Wq_down  = (const float*)d_in[1];
    const float* Wq_up    = (const float*)d_in[2];
    const float* Wkv_down = (const float*)d_in[3];
    const float* k_up     = (const float*)d_in[4];
    const float* v_up     = (const float*)d_in[5];
    const float* Wo       = (const float*)d_in[6];
    float* out = (float*)d_out;

    void* p;
    cudaGetSymbolAddress(&p, g_hidP); uint32_t* hidP = (uint32_t*)p;
    cudaGetSymbolAddress(&p, g_qdP);  uint32_t* qdP  = (uint32_t*)p;
    cudaGetSymbolAddress(&p, g_cP);   uint32_t* cP   = (uint32_t*)p;
    cudaGetSymbolAddress(&p, g_aoP);  uint32_t* aoP  = (uint32_t*)p;
    cudaGetSymbolAddress(&p, g_WqdP); uint32_t* WqdP = (uint32_t*)p;
    cudaGetSymbolAddress(&p, g_WquP); uint32_t* WquP = (uint32_t*)p;
    cudaGetSymbolAddress(&p, g_WkvP); uint32_t* WkvP = (uint32_t*)p;
    cudaGetSymbolAddress(&p, g_WoP);  uint32_t* WoP  = (uint32_t*)p;
    cudaGetSymbolAddress(&p, g_kupT); uint32_t* kupT = (uint32_t*)p;
    cudaGetSymbolAddress(&p, g_vupT); uint32_t* vupT = (uint32_t*)p;
    cudaGetSymbolAddress(&p, g_v);    float* v = (float*)p;
    cudaGetSymbolAddress(&p, g_Qh); uint32_t* Qh = (uint32_t*)p;
    cudaGetSymbolAddress(&p, g_Ql); uint32_t* Ql = (uint32_t*)p;
    cudaGetSymbolAddress(&p, g_Kh); uint32_t* Kh = (uint32_t*)p;
    cudaGetSymbolAddress(&p, g_Kl); uint32_t* Kl = (uint32_t*)p;
    cudaGetSymbolAddress(&p, g_Vh); uint32_t* Vh = (uint32_t*)p;
    cudaGetSymbolAddress(&p, g_Vl); uint32_t* Vl = (uint32_t*)p;

    cudaFuncSetAttribute(attn_tc2,
                         cudaFuncAttributeMaxDynamicSharedMemorySize,
                         AT2_SMEM_BYTES);

    const dim3 thr(256);

    // 0. pack inputs
    pack_rm<<<(BL_ * D_ / 16 + 255) / 256, thr>>>(hidden, hidP, BL_ * D_ / 16);
    pack_rm<<<(RQ_ * D_ / 16 + 255) / 256, thr>>>(Wq_down, WqdP, RQ_ * D_ / 16);
    pack_rm<<<(D_ * RQ_ / 16 + 255) / 256, thr>>>(Wq_up, WquP, D_ * RQ_ / 16);
    pack_rm<<<(RKV_ * D_ / 16 + 255) / 256, thr>>>(Wkv_down, WkvP, RKV_ * D_ / 16);
    pack_rm<<<(D_ * D_ / 16 + 255) / 256, thr>>>(Wo, WoP, D_ * D_ / 16);
    pack_tr<<<256, thr>>>(k_up, kupT);
    pack_tr<<<256, thr>>>(v_up, vupT);

    // 1. qdown = hidden @ Wq_down^T  -> packed
    gemm_p<1><<<dim3(RQ_ / 128, BL_ / 128), thr>>>(
        hidP, WqdP, nullptr, qdP, nullptr, D_, RQ_, 0, 0, 0, 0);
    // 2. q = qdown @ Wq_up^T -> attention Q layout
    gemm_p<2><<<dim3(D_ / 128, BL_ / 128), thr>>>(
        qdP, WquP, nullptr, Qh, Ql, RQ_, 0, 0, 0, 0, 0);
    // 3. c = hidden @ Wkv_down^T -> packed
    gemm_p<1><<<dim3(RKV_ / 128, BL_ / 128), thr>>>(
        hidP, WkvP, nullptr, cP, nullptr, D_, RKV_, 0, 0, 0, 0);
    // 4. k per head -> attention K layout
    gemm_p<2><<<dim3(1, BL_ / 128, H_), thr>>>(
        cP, kupT, nullptr, Kh, Kl, RKV_, 0, 0, (long)HD_ * RKV_, 0, HD_);
    // 5. v per head -> fp32
    gemm_p<0><<<dim3(1, BL_ / 128, H_), thr>>>(
        cP, vupT, v, nullptr, nullptr, RKV_, 0, D_, (long)HD_ * RKV_, HD_, 0);
    // 6. pack V (transpose + split)
    pack_v<<<dim3(L_ / 64, HD_ / 64, B_ * H_), thr>>>(v, Vh, Vl);
    // 7. attention -> packed ao
    attn_tc2<<<dim3(L_ / 128, B_ * H_), thr, AT2_SMEM_BYTES>>>(
        Qh, Ql, Kh, Kl, Vh, Vl, aoP);
    // 8. out = ao @ Wo^T -> fp32
    gemm_p<0><<<dim3(D_ / 128, BL_ / 128), thr>>>(
        aoP, WoP, out, nullptr, nullptr, D_, 0, D_, 0, 0, 0);
}